// round 1
// baseline (speedup 1.0000x reference)
#include <cuda_runtime.h>
#include <math.h>

#define NR 8192
#define CD 1024
#define HD 256
#define FGDIM 64
#define CLDIM 128
#define NS 16   // column splits for sim kernels

// ---------------- device scratch (no allocs allowed) ----------------
__device__ float g_Hf[NR * HD];
__device__ float g_Hc[NR * HD];
__device__ float g_Zf[NR * FGDIM];
__device__ float g_Zc[NR * CLDIM];
__device__ float g_pfg[NS * NR * 2];   // per split, per row: denom, numer
__device__ float g_pcl[NS * NR * 3];   // per split, per row: denomexp, sum_pos, n_pos
__device__ int   g_lbl[NR];
__device__ float g_wgt[NR];
__device__ int   g_fgb[NR];
__device__ int   g_cnt[2];             // [0]=# !ignored, [1]=# fg&!ignored

// ---------------- small kernels ----------------
__global__ void zero_cnt_kernel() { g_cnt[0] = 0; g_cnt[1] = 0; }

__global__ void prep_kernel(const int* __restrict__ lraw, const float* __restrict__ ious) {
    int i = blockIdx.x * blockDim.x + threadIdx.x;
    // Detect int64 vs int32 labels: int64 storage -> every odd word is 0/-1
    // sign-matching its even partner. Random int32 labels fail within a few pairs.
    bool is64 = true;
    #pragma unroll 1
    for (int p = 0; p < 32; ++p) {
        int lo = lraw[2 * p], hi = lraw[2 * p + 1];
        bool ok = (hi == 0 && lo >= 0) || (hi == -1 && lo < 0);
        if (!ok) { is64 = false; break; }
    }
    int l = is64 ? (int)(((const long long*)lraw)[i]) : lraw[i];
    g_lbl[i] = l;
    g_fgb[i] = (l > 0) ? 1 : 0;
    float u = ious[i];
    g_wgt[i] = (u > 0.5f) ? u : 0.0f;

    __shared__ int s0, s1;
    if (threadIdx.x == 0) { s0 = 0; s1 = 0; }
    __syncthreads();
    if (l != -1) atomicAdd(&s0, 1);
    if (l > 0)   atomicAdd(&s1, 1);
    __syncthreads();
    if (threadIdx.x == 0) { atomicAdd(&g_cnt[0], s0); atomicAdd(&g_cnt[1], s1); }
}

// ---------------- generic fp32 GEMM: C = act(A[M,K] @ W[N,K]^T + bias) ----------------
template<int BM, int BN, bool RELU>
__global__ __launch_bounds__((BM / 8) * (BN / 8))
void gemm_bias_kernel(const float* __restrict__ A, const float* __restrict__ W,
                      const float* __restrict__ bias, float* __restrict__ C,
                      int M, int N, int K) {
    constexpr int BK = 16;
    constexpr int TX = BN / 8, TY = BM / 8, NT = TX * TY;
    __shared__ float As[BK][BM + 4];
    __shared__ float Bs[BK][BN + 4];
    const int bm = blockIdx.y * BM, bn = blockIdx.x * BN;
    const int tid = threadIdx.x, tx = tid % TX, ty = tid / TX;

    float acc[8][8];
    #pragma unroll
    for (int a = 0; a < 8; ++a)
        #pragma unroll
        for (int b = 0; b < 8; ++b) acc[a][b] = 0.0f;

    for (int k0 = 0; k0 < K; k0 += BK) {
        #pragma unroll
        for (int i = tid; i < BM * BK / 4; i += NT) {
            int r = i / (BK / 4), c = i % (BK / 4);
            float4 v = *(const float4*)(A + (size_t)(bm + r) * K + k0 + c * 4);
            As[c * 4 + 0][r] = v.x; As[c * 4 + 1][r] = v.y;
            As[c * 4 + 2][r] = v.z; As[c * 4 + 3][r] = v.w;
        }
        #pragma unroll
        for (int i = tid; i < BN * BK / 4; i += NT) {
            int r = i / (BK / 4), c = i % (BK / 4);
            float4 v = *(const float4*)(W + (size_t)(bn + r) * K + k0 + c * 4);
            Bs[c * 4 + 0][r] = v.x; Bs[c * 4 + 1][r] = v.y;
            Bs[c * 4 + 2][r] = v.z; Bs[c * 4 + 3][r] = v.w;
        }
        __syncthreads();
        #pragma unroll 8
        for (int k = 0; k < BK; ++k) {
            float4 a0 = *(const float4*)&As[k][ty * 4];
            float4 a1 = *(const float4*)&As[k][BM / 2 + ty * 4];
            float4 b0 = *(const float4*)&Bs[k][tx * 4];
            float4 b1 = *(const float4*)&Bs[k][BN / 2 + tx * 4];
            float ra[8] = {a0.x, a0.y, a0.z, a0.w, a1.x, a1.y, a1.z, a1.w};
            float rb[8] = {b0.x, b0.y, b0.z, b0.w, b1.x, b1.y, b1.z, b1.w};
            #pragma unroll
            for (int a = 0; a < 8; ++a)
                #pragma unroll
                for (int b = 0; b < 8; ++b)
                    acc[a][b] = fmaf(ra[a], rb[b], acc[a][b]);
        }
        __syncthreads();
    }

    #pragma unroll
    for (int a = 0; a < 8; ++a) {
        int r = bm + ((a < 4) ? ty * 4 + a : BM / 2 + ty * 4 + a - 4);
        #pragma unroll
        for (int h = 0; h < 2; ++h) {
            int cg = bn + (h ? BN / 2 : 0) + tx * 4;
            float4 v;
            float* vp = (float*)&v;
            #pragma unroll
            for (int q = 0; q < 4; ++q) {
                float x = acc[a][h * 4 + q] + bias[cg + q];
                if (RELU) x = fmaxf(x, 0.0f);
                vp[q] = x;
            }
            *(float4*)(C + (size_t)r * N + cg) = v;
        }
    }
}

// ---------------- row L2-normalize (one warp per row) ----------------
__global__ void normalize_kernel(float* __restrict__ Z, int N) {
    int row = blockIdx.x * 8 + (threadIdx.x >> 5);
    int lane = threadIdx.x & 31;
    float ss = 0.0f;
    for (int c = lane; c < N; c += 32) { float v = Z[(size_t)row * N + c]; ss += v * v; }
    #pragma unroll
    for (int o = 16; o; o >>= 1) ss += __shfl_xor_sync(0xffffffffu, ss, o);
    float inv = 1.0f / fmaxf(sqrtf(ss), 1e-8f);
    for (int c = lane; c < N; c += 32) Z[(size_t)row * N + c] *= inv;
}

// ---------------- FMA-only exp(5x) (no MUFU) ----------------
__device__ __forceinline__ float fexp5(float x) {
    // exp(5x) = 2^(x * 5*log2(e)); |x| <= ~1 -> |t| <= 7.3
    const float KE = 7.2134752044448169f;
    const float SH = 12582912.0f;  // 1.5 * 2^23
    float z = fmaf(x, KE, SH);
    int   ei = __float_as_int(z);
    float r = z - SH;              // round-to-nearest integer of t (exact)
    float f = fmaf(x, KE, -r);     // fractional part, [-0.5, 0.5]
    float p = 1.5403530393381609e-4f;
    p = fmaf(p, f, 1.3333558146428443e-3f);
    p = fmaf(p, f, 9.6181291076284771e-3f);
    p = fmaf(p, f, 5.5504108664821580e-2f);
    p = fmaf(p, f, 2.4022650695910071e-1f);
    p = fmaf(p, f, 6.9314718055994531e-1f);
    p = fmaf(p, f, 1.0f);
    return p * __int_as_float((ei - 0x4B400000 + 127) << 23);
}

// ---------------- fused z@z^T + masked exp reductions ----------------
// grid.x: 64 row tiles of 128 rows; grid.y: 16 column splits of 512 cols.
template<int KD, bool CLS>
__global__ __launch_bounds__(256, 2)
void sim_kernel() {
    __shared__ float As[32][132];
    __shared__ float Bs[32][132];
    __shared__ int meta[512];
    const float* Z = CLS ? (const float*)g_Zc : (const float*)g_Zf;
    const int bm = blockIdx.x * 128;
    const int c0 = blockIdx.y * 512;
    const int tid = threadIdx.x, tx = tid & 15, ty = tid >> 4;

    int ri[8], li[8];
    #pragma unroll
    for (int a = 0; a < 8; ++a) {
        ri[a] = (a < 4) ? ty * 4 + a : 64 + ty * 4 + a - 4;
        if (CLS) li[a] = g_lbl[bm + ri[a]];
    }
    for (int i = tid; i < 512; i += 256)
        meta[i] = CLS ? g_lbl[c0 + i] : g_fgb[c0 + i];

    float dn[8], x1[8], x2[8];
    #pragma unroll
    for (int a = 0; a < 8; ++a) { dn[a] = 0.0f; x1[a] = 0.0f; x2[a] = 0.0f; }

    for (int t = 0; t < 4; ++t) {
        const int cb = c0 + t * 128;
        float acc[8][8];
        #pragma unroll
        for (int a = 0; a < 8; ++a)
            #pragma unroll
            for (int b = 0; b < 8; ++b) acc[a][b] = 0.0f;

        for (int kc = 0; kc < KD; kc += 32) {
            __syncthreads();
            #pragma unroll
            for (int i = tid; i < 1024; i += 256) {
                int r = i >> 3, c = i & 7;
                float4 v = *(const float4*)(Z + (size_t)(bm + r) * KD + kc + c * 4);
                As[c * 4 + 0][r] = v.x; As[c * 4 + 1][r] = v.y;
                As[c * 4 + 2][r] = v.z; As[c * 4 + 3][r] = v.w;
            }
            #pragma unroll
            for (int i = tid; i < 1024; i += 256) {
                int r = i >> 3, c = i & 7;
                float4 v = *(const float4*)(Z + (size_t)(cb + r) * KD + kc + c * 4);
                Bs[c * 4 + 0][r] = v.x; Bs[c * 4 + 1][r] = v.y;
                Bs[c * 4 + 2][r] = v.z; Bs[c * 4 + 3][r] = v.w;
            }
            __syncthreads();
            #pragma unroll 8
            for (int k = 0; k < 32; ++k) {
                float4 a0 = *(const float4*)&As[k][ty * 4];
                float4 a1 = *(const float4*)&As[k][64 + ty * 4];
                float4 b0 = *(const float4*)&Bs[k][tx * 4];
                float4 b1 = *(const float4*)&Bs[k][64 + tx * 4];
                float ra[8] = {a0.x, a0.y, a0.z, a0.w, a1.x, a1.y, a1.z, a1.w};
                float rb[8] = {b0.x, b0.y, b0.z, b0.w, b1.x, b1.y, b1.z, b1.w};
                #pragma unroll
                for (int a = 0; a < 8; ++a)
                    #pragma unroll
                    for (int b = 0; b < 8; ++b)
                        acc[a][b] = fmaf(ra[a], rb[b], acc[a][b]);
            }
        }

        // epilogue: exp + masked accumulation (no MUFU)
        #pragma unroll
        for (int a = 0; a < 8; ++a) {
            int gi = bm + ri[a];
            #pragma unroll
            for (int b = 0; b < 8; ++b) {
                int cj = (b < 4) ? tx * 4 + b : 64 + tx * 4 + b - 4;
                int gj = cb + cj;
                float e = fexp5(acc[a][b]);
                bool nd = (gi != gj);
                if (CLS) {
                    int c = meta[t * 128 + cj];
                    if (nd && c >= 0) dn[a] += e;                      // valid_den
                    if (nd && c > 0 && c == li[a]) {                   // positives
                        x1[a] += acc[a][b] * 5.0f;                     // sum of sim
                        x2[a] += 1.0f;                                 // n_pos
                    }
                } else {
                    if (nd) {
                        dn[a] += e;                                    // denom (all j != i)
                        if (meta[t * 128 + cj]) x1[a] += e;            // numer (fg set)
                    }
                }
            }
        }
    }

    // reduce over the 16 tx lanes (within half-warp)
    #pragma unroll
    for (int a = 0; a < 8; ++a) {
        #pragma unroll
        for (int o = 8; o; o >>= 1) {
            dn[a] += __shfl_xor_sync(0xffffffffu, dn[a], o);
            x1[a] += __shfl_xor_sync(0xffffffffu, x1[a], o);
            if (CLS) x2[a] += __shfl_xor_sync(0xffffffffu, x2[a], o);
        }
    }
    if (tx == 0) {
        int s = blockIdx.y;
        #pragma unroll
        for (int a = 0; a < 8; ++a) {
            int gi = bm + ri[a];
            if (CLS) {
                g_pcl[((size_t)s * NR + gi) * 3 + 0] = dn[a];
                g_pcl[((size_t)s * NR + gi) * 3 + 1] = x1[a];
                g_pcl[((size_t)s * NR + gi) * 3 + 2] = x2[a];
            } else {
                g_pfg[((size_t)s * NR + gi) * 2 + 0] = dn[a];
                g_pfg[((size_t)s * NR + gi) * 2 + 1] = x1[a];
            }
        }
    }
}

// ---------------- final deterministic reduction ----------------
__global__ void finalize_kernel(float* __restrict__ out) {
    __shared__ float red[256][4];
    int tid = threadIdx.x;
    float nfg = 0.0f, dfg = 0.0f, ncl = 0.0f, dcl = 0.0f;
    int nfgset = g_cnt[1];
    int nnon = g_cnt[0];
    for (int i = tid; i < NR; i += 256) {
        int l = g_lbl[i];
        if (l > 0) {  // anchor = fg & ~ignore
            float w = g_wgt[i];
            float dn = 0.0f, nm = 0.0f;
            #pragma unroll 1
            for (int s = 0; s < NS; ++s) {
                dn += g_pfg[((size_t)s * NR + i) * 2 + 0];
                nm += g_pfg[((size_t)s * NR + i) * 2 + 1];
            }
            if (nfgset - 1 > 0) {
                float li = -logf((nm + 1e-8f) / (dn + 1e-8f));
                nfg += li * w; dfg += w;
            }
            float dc = 0.0f, sp = 0.0f, np = 0.0f;
            #pragma unroll 1
            for (int s = 0; s < NS; ++s) {
                dc += g_pcl[((size_t)s * NR + i) * 3 + 0];
                sp += g_pcl[((size_t)s * NR + i) * 3 + 1];
                np += g_pcl[((size_t)s * NR + i) * 3 + 2];
            }
            if (np > 0.5f && (nnon - 1) > 0) {
                float li = -(sp - np * logf(dc)) / np;
                ncl += li * w; dcl += w;
            }
        }
    }
    red[tid][0] = nfg; red[tid][1] = dfg; red[tid][2] = ncl; red[tid][3] = dcl;
    __syncthreads();
    for (int s = 128; s > 0; s >>= 1) {
        if (tid < s) {
            red[tid][0] += red[tid + s][0]; red[tid][1] += red[tid + s][1];
            red[tid][2] += red[tid + s][2]; red[tid][3] += red[tid + s][3];
        }
        __syncthreads();
    }
    if (tid == 0) {
        out[0] = red[0][0] / (red[0][1] + 1e-8f);
        out[1] = red[0][2] / (red[0][3] + 1e-12f);
    }
}

// ---------------- launch ----------------
extern "C" void kernel_launch(void* const* d_in, const int* in_sizes, int n_in,
                              void* d_out, int out_size) {
    const float* roi = (const float*)d_in[0];
    const int*   lab = (const int*)d_in[1];
    const float* iou = (const float*)d_in[2];
    const float* w1f = (const float*)d_in[3];
    const float* b1f = (const float*)d_in[4];
    const float* w2f = (const float*)d_in[5];
    const float* b2f = (const float*)d_in[6];
    const float* w1c = (const float*)d_in[7];
    const float* b1c = (const float*)d_in[8];
    const float* w2c = (const float*)d_in[9];
    const float* b2c = (const float*)d_in[10];

    float *Hf, *Hc, *Zf, *Zc;
    cudaGetSymbolAddress((void**)&Hf, g_Hf);
    cudaGetSymbolAddress((void**)&Hc, g_Hc);
    cudaGetSymbolAddress((void**)&Zf, g_Zf);
    cudaGetSymbolAddress((void**)&Zc, g_Zc);

    zero_cnt_kernel<<<1, 1>>>();
    prep_kernel<<<NR / 256, 256>>>(lab, iou);

    // layer 1: H = relu(roi @ W1^T + b1), M=8192 N=256 K=1024
    gemm_bias_kernel<128, 128, true><<<dim3(HD / 128, NR / 128), 256>>>(roi, w1f, b1f, Hf, NR, HD, CD);
    gemm_bias_kernel<128, 128, true><<<dim3(HD / 128, NR / 128), 256>>>(roi, w1c, b1c, Hc, NR, HD, CD);

    // layer 2: Z = H @ W2^T + b2
    gemm_bias_kernel<128, 64, false><<<dim3(1, NR / 128), 128>>>(Hf, w2f, b2f, Zf, NR, FGDIM, HD);
    gemm_bias_kernel<128, 128, false><<<dim3(1, NR / 128), 256>>>(Hc, w2c, b2c, Zc, NR, CLDIM, HD);

    normalize_kernel<<<NR / 8, 256>>>(Zf, FGDIM);
    normalize_kernel<<<NR / 8, 256>>>(Zc, CLDIM);

    sim_kernel<FGDIM, false><<<dim3(64, NS), 256>>>();
    sim_kernel<CLDIM, true><<<dim3(64, NS), 256>>>();

    finalize_kernel<<<1, 256>>>((float*)d_out);
}

// round 3
// speedup vs baseline: 1.8222x; 1.8222x over previous
#include <cuda_runtime.h>
#include <cuda_bf16.h>
#include <math.h>
#include <stdint.h>

#define NR 8192
#define CD 1024
#define HD 256
#define FGDIM 64
#define CLDIM 128
#define NSPL 2          // column splits for sim kernels (grid.y)

// ---------------- device scratch (no allocs allowed) ----------------
__device__ float g_Hf[NR * HD];
__device__ float g_Hc[NR * HD];
__device__ float g_Zf[NR * FGDIM];
__device__ float g_Zc[NR * CLDIM];
__device__ __nv_bfloat16 g_Zfh[NR * FGDIM];
__device__ __nv_bfloat16 g_Zfl[NR * FGDIM];
__device__ __nv_bfloat16 g_Zch[NR * CLDIM];
__device__ __nv_bfloat16 g_Zcl[NR * CLDIM];
__device__ float g_pfg[NSPL * NR * 2];   // per split, per row: denom, numer
__device__ float g_pcl[NSPL * NR * 3];   // per split, per row: denomexp, sum_dot_pos, n_pos
__device__ int   g_lbl[NR];
__device__ float g_wgt[NR];
__device__ int   g_fgb[NR];
__device__ int   g_cnt[2];

// ---------------- helpers ----------------
__device__ __forceinline__ uint32_t smem_u32(const void* p) {
    uint32_t a;
    asm("{ .reg .u64 t; cvta.to.shared.u64 t, %1; cvt.u32.u64 %0, t; }" : "=r"(a) : "l"(p));
    return a;
}

#define LDSM4(r, addr) \
    asm volatile("ldmatrix.sync.aligned.m8n8.x4.shared.b16 {%0,%1,%2,%3}, [%4];" \
        : "=r"((r)[0]), "=r"((r)[1]), "=r"((r)[2]), "=r"((r)[3]) : "r"(addr))

#define MMA16816(d, a, b0, b1) \
    asm volatile("mma.sync.aligned.m16n8k16.row.col.f32.bf16.bf16.f32 " \
        "{%0,%1,%2,%3},{%4,%5,%6,%7},{%8,%9},{%0,%1,%2,%3};" \
        : "+f"((d)[0]), "+f"((d)[1]), "+f"((d)[2]), "+f"((d)[3]) \
        : "r"((a)[0]), "r"((a)[1]), "r"((a)[2]), "r"((a)[3]), "r"(b0), "r"(b1))

// ---------------- small kernels ----------------
__global__ void zero_cnt_kernel() { g_cnt[0] = 0; g_cnt[1] = 0; }

__global__ void prep_kernel(const int* __restrict__ lraw, const float* __restrict__ ious) {
    int i = blockIdx.x * blockDim.x + threadIdx.x;
    bool is64 = true;
    #pragma unroll 1
    for (int p = 0; p < 32; ++p) {
        int lo = lraw[2 * p], hi = lraw[2 * p + 1];
        bool ok = (hi == 0 && lo >= 0) || (hi == -1 && lo < 0);
        if (!ok) { is64 = false; break; }
    }
    int l = is64 ? (int)(((const long long*)lraw)[i]) : lraw[i];
    g_lbl[i] = l;
    g_fgb[i] = (l > 0) ? 1 : 0;
    float u = ious[i];
    g_wgt[i] = (u > 0.5f) ? u : 0.0f;

    __shared__ int s0, s1;
    if (threadIdx.x == 0) { s0 = 0; s1 = 0; }
    __syncthreads();
    if (l != -1) atomicAdd(&s0, 1);
    if (l > 0)   atomicAdd(&s1, 1);
    __syncthreads();
    if (threadIdx.x == 0) { atomicAdd(&g_cnt[0], s0); atomicAdd(&g_cnt[1], s1); }
}

// ---------------- generic fp32 GEMM: C = act(A[M,K] @ W[N,K]^T + bias) ----------------
template<int BM, int BN, bool RELU>
__global__ __launch_bounds__((BM / 8) * (BN / 8))
void gemm_bias_kernel(const float* __restrict__ A, const float* __restrict__ W,
                      const float* __restrict__ bias, float* __restrict__ C,
                      int M, int N, int K) {
    constexpr int BK = 16;
    constexpr int TX = BN / 8, TY = BM / 8, NT = TX * TY;
    __shared__ float As[BK][BM + 4];
    __shared__ float Bs[BK][BN + 4];
    const int bm = blockIdx.y * BM, bn = blockIdx.x * BN;
    const int tid = threadIdx.x, tx = tid % TX, ty = tid / TX;

    float acc[8][8];
    #pragma unroll
    for (int a = 0; a < 8; ++a)
        #pragma unroll
        for (int b = 0; b < 8; ++b) acc[a][b] = 0.0f;

    for (int k0 = 0; k0 < K; k0 += BK) {
        #pragma unroll
        for (int i = tid; i < BM * BK / 4; i += NT) {
            int r = i / (BK / 4), c = i % (BK / 4);
            float4 v = *(const float4*)(A + (size_t)(bm + r) * K + k0 + c * 4);
            As[c * 4 + 0][r] = v.x; As[c * 4 + 1][r] = v.y;
            As[c * 4 + 2][r] = v.z; As[c * 4 + 3][r] = v.w;
        }
        #pragma unroll
        for (int i = tid; i < BN * BK / 4; i += NT) {
            int r = i / (BK / 4), c = i % (BK / 4);
            float4 v = *(const float4*)(W + (size_t)(bn + r) * K + k0 + c * 4);
            Bs[c * 4 + 0][r] = v.x; Bs[c * 4 + 1][r] = v.y;
            Bs[c * 4 + 2][r] = v.z; Bs[c * 4 + 3][r] = v.w;
        }
        __syncthreads();
        #pragma unroll 8
        for (int k = 0; k < BK; ++k) {
            float4 a0 = *(const float4*)&As[k][ty * 4];
            float4 a1 = *(const float4*)&As[k][BM / 2 + ty * 4];
            float4 b0 = *(const float4*)&Bs[k][tx * 4];
            float4 b1 = *(const float4*)&Bs[k][BN / 2 + tx * 4];
            float ra[8] = {a0.x, a0.y, a0.z, a0.w, a1.x, a1.y, a1.z, a1.w};
            float rb[8] = {b0.x, b0.y, b0.z, b0.w, b1.x, b1.y, b1.z, b1.w};
            #pragma unroll
            for (int a = 0; a < 8; ++a)
                #pragma unroll
                for (int b = 0; b < 8; ++b)
                    acc[a][b] = fmaf(ra[a], rb[b], acc[a][b]);
        }
        __syncthreads();
    }

    #pragma unroll
    for (int a = 0; a < 8; ++a) {
        int r = bm + ((a < 4) ? ty * 4 + a : BM / 2 + ty * 4 + a - 4);
        #pragma unroll
        for (int h = 0; h < 2; ++h) {
            int cg = bn + (h ? BN / 2 : 0) + tx * 4;
            float4 v;
            float* vp = (float*)&v;
            #pragma unroll
            for (int q = 0; q < 4; ++q) {
                float x = acc[a][h * 4 + q] + bias[cg + q];
                if (RELU) x = fmaxf(x, 0.0f);
                vp[q] = x;
            }
            *(float4*)(C + (size_t)r * N + cg) = v;
        }
    }
}

// ---------------- row L2-normalize + bf16 hi/lo split (one warp per row) ----------------
template<int KD>
__global__ void norm_conv_kernel(const float* __restrict__ Z,
                                 __nv_bfloat16* __restrict__ Oh,
                                 __nv_bfloat16* __restrict__ Ol) {
    int row = blockIdx.x * 8 + (threadIdx.x >> 5);
    int lane = threadIdx.x & 31;
    float ss = 0.0f;
    #pragma unroll
    for (int c = lane; c < KD; c += 32) { float v = Z[(size_t)row * KD + c]; ss += v * v; }
    #pragma unroll
    for (int o = 16; o; o >>= 1) ss += __shfl_xor_sync(0xffffffffu, ss, o);
    float inv = 1.0f / fmaxf(sqrtf(ss), 1e-8f);
    #pragma unroll
    for (int c = lane; c < KD; c += 32) {
        float v = Z[(size_t)row * KD + c] * inv;
        __nv_bfloat16 h = __float2bfloat16(v);
        Oh[(size_t)row * KD + c] = h;
        Ol[(size_t)row * KD + c] = __float2bfloat16(v - __bfloat162float(h));
    }
}

// ---------------- FMA-only exp(5x), degree-4 (no MUFU) ----------------
__device__ __forceinline__ float fexp5(float x) {
    const float KE = 7.2134752044448169f;  // 5 * log2(e)
    const float SH = 12582912.0f;          // 1.5 * 2^23
    float z = fmaf(x, KE, SH);
    int   ei = __float_as_int(z);
    float r = z - SH;
    float f = fmaf(x, KE, -r);             // [-0.5, 0.5]
    float p = 9.6181291076284771e-3f;
    p = fmaf(p, f, 5.5504108664821580e-2f);
    p = fmaf(p, f, 2.4022650695910071e-1f);
    p = fmaf(p, f, 6.9314718055994531e-1f);
    p = fmaf(p, f, 1.0f);
    return p * __int_as_float((ei - 0x4B400000 + 127) << 23);
}

// ---------------- cp.async tile loader (padded row-major bf16) ----------------
template<int KD>
__device__ __forceinline__ void load_tile(uint32_t dst, const __nv_bfloat16* __restrict__ src, int tid) {
    constexpr int CPR = KD / 8;          // 16B chunks per row
    constexpr int SA = KD * 2 + 16;      // padded row stride (bytes)
    #pragma unroll
    for (int i = tid; i < 128 * CPR; i += 256) {
        int r = i / CPR, c = i % CPR;
        asm volatile("cp.async.cg.shared.global [%0], [%1], 16;"
                     :: "r"(dst + r * SA + c * 16), "l"(src + (size_t)r * KD + c * 8) : "memory");
    }
}

// ---------------- warp-MMA fused sim kernel ----------------
// D = Ah*Bh^T + Ah*Bl^T + Al*Bh^T via mma.sync m16n8k16 bf16; epilogue does
// exp + masked per-row reductions fully in registers (fragment rows).
template<int KD, bool CLS>
__global__ __launch_bounds__(256, 1) void sim_mma_kernel() {
    constexpr int SA = KD * 2 + 16;              // tile row stride bytes
    constexpr int TSZ = 128 * SA;                // bytes per tile
    constexpr int SLAB = NR / NSPL;              // 4096 cols per CTA
    constexpr int TCOLS = SLAB / 128;            // 32 tiles
    constexpr int KSTEPS = KD / 16;
    constexpr int A_HI = SLAB * 4;               // after label slab
    constexpr int A_LO = A_HI + TSZ;
    constexpr int B_OFF = A_LO + TSZ;            // [buf(2)][hi,lo]

    extern __shared__ char smem[];
    int* slbl = (int*)smem;
    uint32_t sb = smem_u32(smem);
    const int tid = threadIdx.x, wid = tid >> 5, lane = tid & 31;
    const int wm = wid & 3, wn = wid >> 2;
    const int bm = blockIdx.x * 128;
    const int c0 = blockIdx.y * SLAB;
    const __nv_bfloat16* Zh = CLS ? g_Zch : g_Zfh;
    const __nv_bfloat16* Zl = CLS ? g_Zcl : g_Zfl;

    for (int i = tid; i < SLAB; i += 256)
        slbl[i] = CLS ? g_lbl[c0 + i] : g_fgb[c0 + i];

    load_tile<KD>(sb + A_HI, Zh + (size_t)bm * KD, tid);
    load_tile<KD>(sb + A_LO, Zl + (size_t)bm * KD, tid);
    load_tile<KD>(sb + B_OFF,       Zh + (size_t)c0 * KD, tid);
    load_tile<KD>(sb + B_OFF + TSZ, Zl + (size_t)c0 * KD, tid);
    asm volatile("cp.async.commit_group;" ::: "memory");

    // per-row-slot state: [ma][rp]
    float dn[2][2] = {{0, 0}, {0, 0}};
    float x1[2][2] = {{0, 0}, {0, 0}};
    float x2[2][2] = {{0, 0}, {0, 0}};
    int li[2][2], gi[2][2];
    #pragma unroll
    for (int ma = 0; ma < 2; ++ma)
        #pragma unroll
        for (int rp = 0; rp < 2; ++rp) {
            gi[ma][rp] = bm + wm * 32 + ma * 16 + rp * 8 + (lane >> 2);
            li[ma][rp] = CLS ? g_lbl[gi[ma][rp]] : 0;
        }

    // ldmatrix per-lane address components
    const uint32_t a_off = (uint32_t)((wm * 32 + (lane & 15)) * SA + (lane >> 4) * 16);
    const uint32_t b_off = (uint32_t)((wn * 64 + ((lane >> 4) << 3) + (lane & 7)) * SA + ((lane >> 3) & 1) * 16);

    float acc[2][8][4];
    #pragma unroll
    for (int ma = 0; ma < 2; ++ma)
        #pragma unroll
        for (int na = 0; na < 8; ++na)
            #pragma unroll
            for (int e = 0; e < 4; ++e) acc[ma][na][e] = 0.0f;

    asm volatile("cp.async.wait_group 0;" ::: "memory");
    __syncthreads();

    for (int t = 0; t < TCOLS; ++t) {
        const uint32_t bcur = sb + B_OFF + (t & 1) * 2 * TSZ;
        if (t + 1 < TCOLS) {
            const uint32_t bnb = sb + B_OFF + ((t + 1) & 1) * 2 * TSZ;
            load_tile<KD>(bnb,       Zh + (size_t)(c0 + (t + 1) * 128) * KD, tid);
            load_tile<KD>(bnb + TSZ, Zl + (size_t)(c0 + (t + 1) * 128) * KD, tid);
            asm volatile("cp.async.commit_group;" ::: "memory");
        }

        #pragma unroll
        for (int ks = 0; ks < KSTEPS; ++ks) {
            uint32_t a_h[2][4], a_l[2][4], b_h[4][4], b_l[4][4];
            const uint32_t kb = ks * 32;
            #pragma unroll
            for (int ma = 0; ma < 2; ++ma) {
                LDSM4(a_h[ma], sb + A_HI + a_off + ma * 16 * SA + kb);
                LDSM4(a_l[ma], sb + A_LO + a_off + ma * 16 * SA + kb);
            }
            #pragma unroll
            for (int g = 0; g < 4; ++g) {
                LDSM4(b_h[g], bcur + b_off + g * 16 * SA + kb);
                LDSM4(b_l[g], bcur + TSZ + b_off + g * 16 * SA + kb);
            }
            #pragma unroll
            for (int ma = 0; ma < 2; ++ma)
                #pragma unroll
                for (int g = 0; g < 4; ++g) {
                    MMA16816(acc[ma][2 * g],     a_h[ma], b_h[g][0], b_h[g][1]);
                    MMA16816(acc[ma][2 * g + 1], a_h[ma], b_h[g][2], b_h[g][3]);
                    MMA16816(acc[ma][2 * g],     a_h[ma], b_l[g][0], b_l[g][1]);
                    MMA16816(acc[ma][2 * g + 1], a_h[ma], b_l[g][2], b_l[g][3]);
                    MMA16816(acc[ma][2 * g],     a_l[ma], b_h[g][0], b_h[g][1]);
                    MMA16816(acc[ma][2 * g + 1], a_l[ma], b_h[g][2], b_h[g][3]);
                }
        }

        // epilogue for this 128x128 tile
        const int tb = t * 128;
        const int cbm = c0 + tb;
        #pragma unroll
        for (int ma = 0; ma < 2; ++ma) {
            const int d0 = gi[ma][0] - cbm;   // diag col (local) for row-slot 0
            const int d1 = gi[ma][1] - cbm;   // for row-slot 1
            #pragma unroll
            for (int na = 0; na < 8; ++na) {
                const int cA = wn * 64 + na * 8 + (lane & 3) * 2;
                const int2 lp = *(const int2*)(slbl + tb + cA);
                float* c = acc[ma][na];
                #pragma unroll
                for (int e = 0; e < 4; ++e) {
                    const float v = c[e];
                    const int col = cA + (e & 1);
                    const int l = (e & 1) ? lp.y : lp.x;
                    const int rp = e >> 1;
                    const bool nd = col != ((rp) ? d1 : d0);
                    const float ex = fexp5(v);
                    if (CLS) {
                        if (nd && l >= 0) dn[ma][rp] += ex;
                        if (nd && l == li[ma][rp]) { x1[ma][rp] += v; x2[ma][rp] += 1.0f; }
                    } else {
                        if (nd) { dn[ma][rp] += ex; if (l) x1[ma][rp] += ex; }
                    }
                    c[e] = 0.0f;
                }
            }
        }

        if (t + 1 < TCOLS) {
            asm volatile("cp.async.wait_group 0;" ::: "memory");
        }
        __syncthreads();
    }

    // quad reduction (lanes g*4..g*4+3 share rows)
    #pragma unroll
    for (int ma = 0; ma < 2; ++ma)
        #pragma unroll
        for (int rp = 0; rp < 2; ++rp) {
            #pragma unroll
            for (int o = 1; o <= 2; o <<= 1) {
                dn[ma][rp] += __shfl_xor_sync(0xffffffffu, dn[ma][rp], o);
                x1[ma][rp] += __shfl_xor_sync(0xffffffffu, x1[ma][rp], o);
                if (CLS) x2[ma][rp] += __shfl_xor_sync(0xffffffffu, x2[ma][rp], o);
            }
        }

    float* red = (float*)smem;   // reuse label slab (all reads done, post-barrier)
    __syncthreads();
    if (wn == 1 && (lane & 3) == 0) {
        #pragma unroll
        for (int ma = 0; ma < 2; ++ma)
            #pragma unroll
            for (int rp = 0; rp < 2; ++rp) {
                int rl = wm * 32 + ma * 16 + rp * 8 + (lane >> 2);
                red[rl * 3 + 0] = dn[ma][rp];
                red[rl * 3 + 1] = x1[ma][rp];
                red[rl * 3 + 2] = x2[ma][rp];
            }
    }
    __syncthreads();
    if (wn == 0 && (lane & 3) == 0) {
        const int s = blockIdx.y;
        #pragma unroll
        for (int ma = 0; ma < 2; ++ma)
            #pragma unroll
            for (int rp = 0; rp < 2; ++rp) {
                int rl = wm * 32 + ma * 16 + rp * 8 + (lane >> 2);
                float a = dn[ma][rp] + red[rl * 3 + 0];
                float b = x1[ma][rp] + red[rl * 3 + 1];
                float cc = x2[ma][rp] + red[rl * 3 + 2];
                int g = bm + rl;
                if (CLS) {
                    g_pcl[((size_t)s * NR + g) * 3 + 0] = a;
                    g_pcl[((size_t)s * NR + g) * 3 + 1] = b;
                    g_pcl[((size_t)s * NR + g) * 3 + 2] = cc;
                } else {
                    g_pfg[((size_t)s * NR + g) * 2 + 0] = a;
                    g_pfg[((size_t)s * NR + g) * 2 + 1] = b;
                }
            }
    }
}

// ---------------- final deterministic reduction ----------------
__global__ void finalize_kernel(float* __restrict__ out) {
    __shared__ float red[256][4];
    int tid = threadIdx.x;
    float nfg = 0.0f, dfg = 0.0f, ncl = 0.0f, dcl = 0.0f;
    int nfgset = g_cnt[1];
    int nnon = g_cnt[0];
    for (int i = tid; i < NR; i += 256) {
        int l = g_lbl[i];
        if (l > 0) {
            float w = g_wgt[i];
            float dnv = 0.0f, nm = 0.0f;
            #pragma unroll
            for (int s = 0; s < NSPL; ++s) {
                dnv += g_pfg[((size_t)s * NR + i) * 2 + 0];
                nm  += g_pfg[((size_t)s * NR + i) * 2 + 1];
            }
            if (nfgset - 1 > 0) {
                float li = -logf((nm + 1e-8f) / (dnv + 1e-8f));
                nfg += li * w; dfg += w;
            }
            float dc = 0.0f, sp = 0.0f, np = 0.0f;
            #pragma unroll
            for (int s = 0; s < NSPL; ++s) {
                dc += g_pcl[((size_t)s * NR + i) * 3 + 0];
                sp += g_pcl[((size_t)s * NR + i) * 3 + 1];
                np += g_pcl[((size_t)s * NR + i) * 3 + 2];
            }
            if (np > 0.5f && (nnon - 1) > 0) {
                float li = -(5.0f * sp - np * logf(dc)) / np;   // sim = dot / TAU, TAU = 0.2
                ncl += li * w; dcl += w;
            }
        }
    }
    red[tid][0] = nfg; red[tid][1] = dfg; red[tid][2] = ncl; red[tid][3] = dcl;
    __syncthreads();
    for (int s = 128; s > 0; s >>= 1) {
        if (tid < s) {
            red[tid][0] += red[tid + s][0]; red[tid][1] += red[tid + s][1];
            red[tid][2] += red[tid + s][2]; red[tid][3] += red[tid + s][3];
        }
        __syncthreads();
    }
    if (tid == 0) {
        out[0] = red[0][0] / (red[0][1] + 1e-8f);
        out[1] = red[0][2] / (red[0][3] + 1e-12f);
    }
}

// ---------------- launch ----------------
extern "C" void kernel_launch(void* const* d_in, const int* in_sizes, int n_in,
                              void* d_out, int out_size) {
    const float* roi = (const float*)d_in[0];
    const int*   lab = (const int*)d_in[1];
    const float* iou = (const float*)d_in[2];
    const float* w1f = (const float*)d_in[3];
    const float* b1f = (const float*)d_in[4];
    const float* w2f = (const float*)d_in[5];
    const float* b2f = (const float*)d_in[6];
    const float* w1c = (const float*)d_in[7];
    const float* b1c = (const float*)d_in[8];
    const float* w2c = (const float*)d_in[9];
    const float* b2c = (const float*)d_in[10];

    float *Hf, *Hc, *Zf, *Zc;
    __nv_bfloat16 *Zfh, *Zfl, *Zch, *Zcl;
    cudaGetSymbolAddress((void**)&Hf, g_Hf);
    cudaGetSymbolAddress((void**)&Hc, g_Hc);
    cudaGetSymbolAddress((void**)&Zf, g_Zf);
    cudaGetSymbolAddress((void**)&Zc, g_Zc);
    cudaGetSymbolAddress((void**)&Zfh, g_Zfh);
    cudaGetSymbolAddress((void**)&Zfl, g_Zfl);
    cudaGetSymbolAddress((void**)&Zch, g_Zch);
    cudaGetSymbolAddress((void**)&Zcl, g_Zcl);

    // dynamic smem: label slab + A hi/lo + B hi/lo double-buffered
    constexpr int SMEM_FG  = (NR / NSPL) * 4 + 6 * 128 * (FGDIM * 2 + 16);  // 126976
    constexpr int SMEM_CLS = (NR / NSPL) * 4 + 6 * 128 * (CLDIM * 2 + 16);  // 225280
    cudaFuncSetAttribute(sim_mma_kernel<FGDIM, false>, cudaFuncAttributeMaxDynamicSharedMemorySize, SMEM_FG);
    cudaFuncSetAttribute(sim_mma_kernel<CLDIM, true>,  cudaFuncAttributeMaxDynamicSharedMemorySize, SMEM_CLS);

    zero_cnt_kernel<<<1, 1>>>();
    prep_kernel<<<NR / 256, 256>>>(lab, iou);

    // layer 1: H = relu(roi @ W1^T + b1)
    gemm_bias_kernel<128, 128, true><<<dim3(HD / 128, NR / 128), 256>>>(roi, w1f, b1f, Hf, NR, HD, CD);
    gemm_bias_kernel<128, 128, true><<<dim3(HD / 128, NR / 128), 256>>>(roi, w1c, b1c, Hc, NR, HD, CD);

    // layer 2: Z = H @ W2^T + b2
    gemm_bias_kernel<128, 64, false><<<dim3(1, NR / 128), 128>>>(Hf, w2f, b2f, Zf, NR, FGDIM, HD);
    gemm_bias_kernel<128, 128, false><<<dim3(1, NR / 128), 256>>>(Hc, w2c, b2c, Zc, NR, CLDIM, HD);

    // normalize + bf16 hi/lo split
    norm_conv_kernel<FGDIM><<<NR / 8, 256>>>(Zf, Zfh, Zfl);
    norm_conv_kernel<CLDIM><<<NR / 8, 256>>>(Zc, Zch, Zcl);

    // fused tensor-core sim + reductions
    sim_mma_kernel<FGDIM, false><<<dim3(64, NSPL), 256, SMEM_FG>>>();
    sim_mma_kernel<CLDIM, true><<<dim3(64, NSPL), 256, SMEM_CLS>>>();

    finalize_kernel<<<1, 256>>>((float*)d_out);
}

// round 4
// speedup vs baseline: 2.4063x; 1.3206x over previous
#include <cuda_runtime.h>
#include <cuda_bf16.h>
#include <math.h>
#include <stdint.h>

#define NR 8192
#define CD 1024
#define HD 256
#define FGDIM 64
#define CLDIM 128
#define NSPL 2          // column splits for sim kernels (grid.y)

// ---------------- device scratch (no allocs allowed) ----------------
__device__ __nv_bfloat16 g_Xh[NR * CD];
__device__ __nv_bfloat16 g_Xl[NR * CD];
__device__ __nv_bfloat16 g_W1fh[HD * CD];
__device__ __nv_bfloat16 g_W1fl[HD * CD];
__device__ __nv_bfloat16 g_W1ch[HD * CD];
__device__ __nv_bfloat16 g_W1cl[HD * CD];
__device__ __nv_bfloat16 g_W2fh[FGDIM * HD];
__device__ __nv_bfloat16 g_W2fl[FGDIM * HD];
__device__ __nv_bfloat16 g_W2ch[CLDIM * HD];
__device__ __nv_bfloat16 g_W2cl[CLDIM * HD];
__device__ __nv_bfloat16 g_Hfh[NR * HD];
__device__ __nv_bfloat16 g_Hfl[NR * HD];
__device__ __nv_bfloat16 g_Hch[NR * HD];
__device__ __nv_bfloat16 g_Hcl[NR * HD];
__device__ float g_Zf[NR * FGDIM];
__device__ float g_Zc[NR * CLDIM];
__device__ __nv_bfloat16 g_Zfh[NR * FGDIM];
__device__ __nv_bfloat16 g_Zfl[NR * FGDIM];
__device__ __nv_bfloat16 g_Zch[NR * CLDIM];
__device__ __nv_bfloat16 g_Zcl[NR * CLDIM];
__device__ float g_pfg[NSPL * NR * 2];
__device__ float g_pcl[NSPL * NR * 3];
__device__ int   g_lbl[NR];
__device__ float g_wgt[NR];
__device__ int   g_fgb[NR];
__device__ int   g_cnt[2];

// ---------------- helpers ----------------
__device__ __forceinline__ uint32_t smem_u32(const void* p) {
    uint32_t a;
    asm("{ .reg .u64 t; cvta.to.shared.u64 t, %1; cvt.u32.u64 %0, t; }" : "=r"(a) : "l"(p));
    return a;
}

#define LDSM4(r, addr) \
    asm volatile("ldmatrix.sync.aligned.m8n8.x4.shared.b16 {%0,%1,%2,%3}, [%4];" \
        : "=r"((r)[0]), "=r"((r)[1]), "=r"((r)[2]), "=r"((r)[3]) : "r"(addr))

#define MMA16816(d, a, b0, b1) \
    asm volatile("mma.sync.aligned.m16n8k16.row.col.f32.bf16.bf16.f32 " \
        "{%0,%1,%2,%3},{%4,%5,%6,%7},{%8,%9},{%0,%1,%2,%3};" \
        : "+f"((d)[0]), "+f"((d)[1]), "+f"((d)[2]), "+f"((d)[3]) \
        : "r"((a)[0]), "r"((a)[1]), "r"((a)[2]), "r"((a)[3]), "r"(b0), "r"(b1))

// ---------------- small kernels ----------------
__global__ void zero_cnt_kernel() { g_cnt[0] = 0; g_cnt[1] = 0; }

__global__ void prep_kernel(const int* __restrict__ lraw, const float* __restrict__ ious) {
    int i = blockIdx.x * blockDim.x + threadIdx.x;
    bool is64 = true;
    #pragma unroll 1
    for (int p = 0; p < 32; ++p) {
        int lo = lraw[2 * p], hi = lraw[2 * p + 1];
        bool ok = (hi == 0 && lo >= 0) || (hi == -1 && lo < 0);
        if (!ok) { is64 = false; break; }
    }
    int l = is64 ? (int)(((const long long*)lraw)[i]) : lraw[i];
    g_lbl[i] = l;
    g_fgb[i] = (l > 0) ? 1 : 0;
    float u = ious[i];
    g_wgt[i] = (u > 0.5f) ? u : 0.0f;

    __shared__ int s0, s1;
    if (threadIdx.x == 0) { s0 = 0; s1 = 0; }
    __syncthreads();
    if (l != -1) atomicAdd(&s0, 1);
    if (l > 0)   atomicAdd(&s1, 1);
    __syncthreads();
    if (threadIdx.x == 0) { atomicAdd(&g_cnt[0], s0); atomicAdd(&g_cnt[1], s1); }
}

// ---------------- fp32 -> bf16 hi/lo split conversion ----------------
__global__ void conv_hl_kernel(const float* __restrict__ s,
                               __nv_bfloat16* __restrict__ h,
                               __nv_bfloat16* __restrict__ l, int n4) {
    int i = blockIdx.x * blockDim.x + threadIdx.x;
    if (i >= n4) return;
    float4 v = ((const float4*)s)[i];
    __nv_bfloat162 h0, h1, l0, l1;
    h0.x = __float2bfloat16(v.x); h0.y = __float2bfloat16(v.y);
    h1.x = __float2bfloat16(v.z); h1.y = __float2bfloat16(v.w);
    l0.x = __float2bfloat16(v.x - __bfloat162float(h0.x));
    l0.y = __float2bfloat16(v.y - __bfloat162float(h0.y));
    l1.x = __float2bfloat16(v.z - __bfloat162float(h1.x));
    l1.y = __float2bfloat16(v.w - __bfloat162float(h1.y));
    ((__nv_bfloat162*)h)[i * 2] = h0; ((__nv_bfloat162*)h)[i * 2 + 1] = h1;
    ((__nv_bfloat162*)l)[i * 2] = l0; ((__nv_bfloat162*)l)[i * 2 + 1] = l1;
}

// ---------------- cp.async bf16 tile loader (BK=64, padded stride 144B) ----------------
__device__ __forceinline__ void ld_tile64(uint32_t dst, const __nv_bfloat16* __restrict__ src,
                                          int rows, int K, int tid) {
    #pragma unroll 4
    for (int i = tid; i < rows * 8; i += 256) {
        int r = i >> 3, c = i & 7;
        asm volatile("cp.async.cg.shared.global [%0], [%1], 16;"
                     :: "r"(dst + r * 144 + c * 16), "l"(src + (size_t)r * K + c * 8) : "memory");
    }
}

// ---------------- MMA GEMM: C = act(A[M,K] @ W[N,K]^T + bias) via bf16 hi/lo ----------------
// RELU_SPLIT: relu then store bf16 hi/lo pair; else store fp32.
template<int BN, bool RELU_SPLIT>
__global__ __launch_bounds__(256) void mma_gemm(
    const __nv_bfloat16* __restrict__ Ah0, const __nv_bfloat16* __restrict__ Al0,
    const __nv_bfloat16* __restrict__ Ah1, const __nv_bfloat16* __restrict__ Al1,
    const __nv_bfloat16* __restrict__ Wh0, const __nv_bfloat16* __restrict__ Wl0,
    const __nv_bfloat16* __restrict__ Wh1, const __nv_bfloat16* __restrict__ Wl1,
    const float* __restrict__ bias0, const float* __restrict__ bias1,
    void* __restrict__ o0a, void* __restrict__ o0b,
    void* __restrict__ o1a, void* __restrict__ o1b,
    int N, int K) {
    constexpr int SA = 144;                 // 64 bf16 + 16B pad
    constexpr int ATS = 128 * SA;
    constexpr int BTS = BN * SA;
    constexpr int STG = 2 * ATS + 2 * BTS;  // [Ah, Al, Bh, Bl]
    constexpr int NG = BN / 32;             // ldsm B groups per warp
    constexpr int NF = 2 * NG;              // n8 frags per warp

    extern __shared__ char smem[];
    uint32_t sb = smem_u32(smem);
    const int tid = threadIdx.x, wid = tid >> 5, lane = tid & 31;
    const int wm = wid & 3, wn = wid >> 2;
    const int z = blockIdx.z;
    const int bm = blockIdx.y * 128, bn = blockIdx.x * BN;

    const __nv_bfloat16* Ah = z ? Ah1 : Ah0;
    const __nv_bfloat16* Al = z ? Al1 : Al0;
    const __nv_bfloat16* Wh = z ? Wh1 : Wh0;
    const __nv_bfloat16* Wl = z ? Wl1 : Wl0;
    const float* bias = z ? bias1 : bias0;

    const int KC = K >> 6;

    ld_tile64(sb, Ah + (size_t)bm * K, 128, K, tid);
    ld_tile64(sb + ATS, Al + (size_t)bm * K, 128, K, tid);
    ld_tile64(sb + 2 * ATS, Wh + (size_t)bn * K, BN, K, tid);
    ld_tile64(sb + 2 * ATS + BTS, Wl + (size_t)bn * K, BN, K, tid);
    asm volatile("cp.async.commit_group;" ::: "memory");

    float acc[2][NF][4];
    #pragma unroll
    for (int ma = 0; ma < 2; ++ma)
        #pragma unroll
        for (int nf = 0; nf < NF; ++nf)
            #pragma unroll
            for (int e = 0; e < 4; ++e) acc[ma][nf][e] = 0.0f;

    const uint32_t a_off = (uint32_t)((wm * 32 + (lane & 15)) * SA + (lane >> 4) * 16);
    const uint32_t b_off = (uint32_t)((wn * (BN / 2) + ((lane >> 4) << 3) + (lane & 7)) * SA + ((lane >> 3) & 1) * 16);

    for (int kc = 0; kc < KC; ++kc) {
        const uint32_t cur = sb + (kc & 1) * STG;
        if (kc + 1 < KC) {
            const uint32_t nxt = sb + ((kc + 1) & 1) * STG;
            const int ko = (kc + 1) * 64;
            ld_tile64(nxt, Ah + (size_t)bm * K + ko, 128, K, tid);
            ld_tile64(nxt + ATS, Al + (size_t)bm * K + ko, 128, K, tid);
            ld_tile64(nxt + 2 * ATS, Wh + (size_t)bn * K + ko, BN, K, tid);
            ld_tile64(nxt + 2 * ATS + BTS, Wl + (size_t)bn * K + ko, BN, K, tid);
            asm volatile("cp.async.commit_group;" ::: "memory");
            asm volatile("cp.async.wait_group 1;" ::: "memory");
        } else {
            asm volatile("cp.async.wait_group 0;" ::: "memory");
        }
        __syncthreads();

        #pragma unroll
        for (int ks = 0; ks < 4; ++ks) {
            const uint32_t kb = ks * 32;
            uint32_t a_h[2][4], a_l[2][4], b_h[NG][4], b_l[NG][4];
            #pragma unroll
            for (int ma = 0; ma < 2; ++ma) {
                LDSM4(a_h[ma], cur + a_off + ma * 16 * SA + kb);
                LDSM4(a_l[ma], cur + ATS + a_off + ma * 16 * SA + kb);
            }
            #pragma unroll
            for (int g = 0; g < NG; ++g) {
                LDSM4(b_h[g], cur + 2 * ATS + b_off + g * 16 * SA + kb);
                LDSM4(b_l[g], cur + 2 * ATS + BTS + b_off + g * 16 * SA + kb);
            }
            #pragma unroll
            for (int ma = 0; ma < 2; ++ma)
                #pragma unroll
                for (int g = 0; g < NG; ++g) {
                    MMA16816(acc[ma][2 * g],     a_h[ma], b_h[g][0], b_h[g][1]);
                    MMA16816(acc[ma][2 * g + 1], a_h[ma], b_h[g][2], b_h[g][3]);
                    MMA16816(acc[ma][2 * g],     a_h[ma], b_l[g][0], b_l[g][1]);
                    MMA16816(acc[ma][2 * g + 1], a_h[ma], b_l[g][2], b_l[g][3]);
                    MMA16816(acc[ma][2 * g],     a_l[ma], b_h[g][0], b_h[g][1]);
                    MMA16816(acc[ma][2 * g + 1], a_l[ma], b_h[g][2], b_h[g][3]);
                }
        }
        __syncthreads();
    }

    // epilogue
    #pragma unroll
    for (int ma = 0; ma < 2; ++ma)
        #pragma unroll
        for (int nf = 0; nf < NF; ++nf)
            #pragma unroll
            for (int rp = 0; rp < 2; ++rp) {
                const int r = bm + wm * 32 + ma * 16 + rp * 8 + (lane >> 2);
                const int c = bn + wn * (BN / 2) + nf * 8 + (lane & 3) * 2;
                float2 bb = *(const float2*)(bias + c);
                float v0 = acc[ma][nf][rp * 2 + 0] + bb.x;
                float v1 = acc[ma][nf][rp * 2 + 1] + bb.y;
                if (RELU_SPLIT) {
                    v0 = fmaxf(v0, 0.0f); v1 = fmaxf(v1, 0.0f);
                    __nv_bfloat16* oh = (__nv_bfloat16*)(z ? o1a : o0a);
                    __nv_bfloat16* ol = (__nv_bfloat16*)(z ? o1b : o0b);
                    __nv_bfloat162 hv, lv;
                    hv.x = __float2bfloat16(v0); hv.y = __float2bfloat16(v1);
                    lv.x = __float2bfloat16(v0 - __bfloat162float(hv.x));
                    lv.y = __float2bfloat16(v1 - __bfloat162float(hv.y));
                    *(__nv_bfloat162*)(oh + (size_t)r * N + c) = hv;
                    *(__nv_bfloat162*)(ol + (size_t)r * N + c) = lv;
                } else {
                    float* of = (float*)(z ? o1a : o0a);
                    float2 ov; ov.x = v0; ov.y = v1;
                    *(float2*)(of + (size_t)r * N + c) = ov;
                }
            }
}

// ---------------- row L2-normalize + bf16 hi/lo split ----------------
template<int KD>
__global__ void norm_conv_kernel(const float* __restrict__ Z,
                                 __nv_bfloat16* __restrict__ Oh,
                                 __nv_bfloat16* __restrict__ Ol) {
    int row = blockIdx.x * 8 + (threadIdx.x >> 5);
    int lane = threadIdx.x & 31;
    float ss = 0.0f;
    #pragma unroll
    for (int c = lane; c < KD; c += 32) { float v = Z[(size_t)row * KD + c]; ss += v * v; }
    #pragma unroll
    for (int o = 16; o; o >>= 1) ss += __shfl_xor_sync(0xffffffffu, ss, o);
    float inv = 1.0f / fmaxf(sqrtf(ss), 1e-8f);
    #pragma unroll
    for (int c = lane; c < KD; c += 32) {
        float v = Z[(size_t)row * KD + c] * inv;
        __nv_bfloat16 h = __float2bfloat16(v);
        Oh[(size_t)row * KD + c] = h;
        Ol[(size_t)row * KD + c] = __float2bfloat16(v - __bfloat162float(h));
    }
}

// ---------------- FMA-only exp(5x), degree-4 (no MUFU) ----------------
__device__ __forceinline__ float fexp5(float x) {
    const float KE = 7.2134752044448169f;
    const float SH = 12582912.0f;
    float z = fmaf(x, KE, SH);
    int   ei = __float_as_int(z);
    float r = z - SH;
    float f = fmaf(x, KE, -r);
    float p = 9.6181291076284771e-3f;
    p = fmaf(p, f, 5.5504108664821580e-2f);
    p = fmaf(p, f, 2.4022650695910071e-1f);
    p = fmaf(p, f, 6.9314718055994531e-1f);
    p = fmaf(p, f, 1.0f);
    return p * __int_as_float((ei - 0x4B400000 + 127) << 23);
}

// ---------------- cp.async tile loader for sim (full K resident) ----------------
template<int KD>
__device__ __forceinline__ void load_tile(uint32_t dst, const __nv_bfloat16* __restrict__ src, int tid) {
    constexpr int CPR = KD / 8;
    constexpr int SA = KD * 2 + 16;
    #pragma unroll
    for (int i = tid; i < 128 * CPR; i += 256) {
        int r = i / CPR, c = i % CPR;
        asm volatile("cp.async.cg.shared.global [%0], [%1], 16;"
                     :: "r"(dst + r * SA + c * 16), "l"(src + (size_t)r * KD + c * 8) : "memory");
    }
}

// ---------------- warp-MMA fused sim kernel (unchanged from round 3) ----------------
template<int KD, bool CLS>
__global__ __launch_bounds__(256, 1) void sim_mma_kernel() {
    constexpr int SA = KD * 2 + 16;
    constexpr int TSZ = 128 * SA;
    constexpr int SLAB = NR / NSPL;
    constexpr int TCOLS = SLAB / 128;
    constexpr int KSTEPS = KD / 16;
    constexpr int A_HI = SLAB * 4;
    constexpr int A_LO = A_HI + TSZ;
    constexpr int B_OFF = A_LO + TSZ;

    extern __shared__ char smem[];
    int* slbl = (int*)smem;
    uint32_t sb = smem_u32(smem);
    const int tid = threadIdx.x, wid = tid >> 5, lane = tid & 31;
    const int wm = wid & 3, wn = wid >> 2;
    const int bm = blockIdx.x * 128;
    const int c0 = blockIdx.y * SLAB;
    const __nv_bfloat16* Zh = CLS ? g_Zch : g_Zfh;
    const __nv_bfloat16* Zl = CLS ? g_Zcl : g_Zfl;

    for (int i = tid; i < SLAB; i += 256)
        slbl[i] = CLS ? g_lbl[c0 + i] : g_fgb[c0 + i];

    load_tile<KD>(sb + A_HI, Zh + (size_t)bm * KD, tid);
    load_tile<KD>(sb + A_LO, Zl + (size_t)bm * KD, tid);
    load_tile<KD>(sb + B_OFF,       Zh + (size_t)c0 * KD, tid);
    load_tile<KD>(sb + B_OFF + TSZ, Zl + (size_t)c0 * KD, tid);
    asm volatile("cp.async.commit_group;" ::: "memory");

    float dn[2][2] = {{0, 0}, {0, 0}};
    float x1[2][2] = {{0, 0}, {0, 0}};
    float x2[2][2] = {{0, 0}, {0, 0}};
    int li[2][2], gi[2][2];
    #pragma unroll
    for (int ma = 0; ma < 2; ++ma)
        #pragma unroll
        for (int rp = 0; rp < 2; ++rp) {
            gi[ma][rp] = bm + wm * 32 + ma * 16 + rp * 8 + (lane >> 2);
            li[ma][rp] = CLS ? g_lbl[gi[ma][rp]] : 0;
        }

    const uint32_t a_off = (uint32_t)((wm * 32 + (lane & 15)) * SA + (lane >> 4) * 16);
    const uint32_t b_off = (uint32_t)((wn * 64 + ((lane >> 4) << 3) + (lane & 7)) * SA + ((lane >> 3) & 1) * 16);

    float acc[2][8][4];
    #pragma unroll
    for (int ma = 0; ma < 2; ++ma)
        #pragma unroll
        for (int na = 0; na < 8; ++na)
            #pragma unroll
            for (int e = 0; e < 4; ++e) acc[ma][na][e] = 0.0f;

    asm volatile("cp.async.wait_group 0;" ::: "memory");
    __syncthreads();

    for (int t = 0; t < TCOLS; ++t) {
        const uint32_t bcur = sb + B_OFF + (t & 1) * 2 * TSZ;
        if (t + 1 < TCOLS) {
            const uint32_t bnb = sb + B_OFF + ((t + 1) & 1) * 2 * TSZ;
            load_tile<KD>(bnb,       Zh + (size_t)(c0 + (t + 1) * 128) * KD, tid);
            load_tile<KD>(bnb + TSZ, Zl + (size_t)(c0 + (t + 1) * 128) * KD, tid);
            asm volatile("cp.async.commit_group;" ::: "memory");
        }

        #pragma unroll
        for (int ks = 0; ks < KSTEPS; ++ks) {
            uint32_t a_h[2][4], a_l[2][4], b_h[4][4], b_l[4][4];
            const uint32_t kb = ks * 32;
            #pragma unroll
            for (int ma = 0; ma < 2; ++ma) {
                LDSM4(a_h[ma], sb + A_HI + a_off + ma * 16 * SA + kb);
                LDSM4(a_l[ma], sb + A_LO + a_off + ma * 16 * SA + kb);
            }
            #pragma unroll
            for (int g = 0; g < 4; ++g) {
                LDSM4(b_h[g], bcur + b_off + g * 16 * SA + kb);
                LDSM4(b_l[g], bcur + TSZ + b_off + g * 16 * SA + kb);
            }
            #pragma unroll
            for (int ma = 0; ma < 2; ++ma)
                #pragma unroll
                for (int g = 0; g < 4; ++g) {
                    MMA16816(acc[ma][2 * g],     a_h[ma], b_h[g][0], b_h[g][1]);
                    MMA16816(acc[ma][2 * g + 1], a_h[ma], b_h[g][2], b_h[g][3]);
                    MMA16816(acc[ma][2 * g],     a_h[ma], b_l[g][0], b_l[g][1]);
                    MMA16816(acc[ma][2 * g + 1], a_h[ma], b_l[g][2], b_l[g][3]);
                    MMA16816(acc[ma][2 * g],     a_l[ma], b_h[g][0], b_h[g][1]);
                    MMA16816(acc[ma][2 * g + 1], a_l[ma], b_h[g][2], b_h[g][3]);
                }
        }

        const int tb = t * 128;
        const int cbm = c0 + tb;
        #pragma unroll
        for (int ma = 0; ma < 2; ++ma) {
            const int d0 = gi[ma][0] - cbm;
            const int d1 = gi[ma][1] - cbm;
            #pragma unroll
            for (int na = 0; na < 8; ++na) {
                const int cA = wn * 64 + na * 8 + (lane & 3) * 2;
                const int2 lp = *(const int2*)(slbl + tb + cA);
                float* c = acc[ma][na];
                #pragma unroll
                for (int e = 0; e < 4; ++e) {
                    const float v = c[e];
                    const int col = cA + (e & 1);
                    const int l = (e & 1) ? lp.y : lp.x;
                    const int rp = e >> 1;
                    const bool nd = col != ((rp) ? d1 : d0);
                    const float ex = fexp5(v);
                    if (CLS) {
                        if (nd && l >= 0) dn[ma][rp] += ex;
                        if (nd && l == li[ma][rp]) { x1[ma][rp] += v; x2[ma][rp] += 1.0f; }
                    } else {
                        if (nd) { dn[ma][rp] += ex; if (l) x1[ma][rp] += ex; }
                    }
                    c[e] = 0.0f;
                }
            }
        }

        if (t + 1 < TCOLS) {
            asm volatile("cp.async.wait_group 0;" ::: "memory");
        }
        __syncthreads();
    }

    #pragma unroll
    for (int ma = 0; ma < 2; ++ma)
        #pragma unroll
        for (int rp = 0; rp < 2; ++rp) {
            #pragma unroll
            for (int o = 1; o <= 2; o <<= 1) {
                dn[ma][rp] += __shfl_xor_sync(0xffffffffu, dn[ma][rp], o);
                x1[ma][rp] += __shfl_xor_sync(0xffffffffu, x1[ma][rp], o);
                if (CLS) x2[ma][rp] += __shfl_xor_sync(0xffffffffu, x2[ma][rp], o);
            }
        }

    float* red = (float*)smem;
    __syncthreads();
    if (wn == 1 && (lane & 3) == 0) {
        #pragma unroll
        for (int ma = 0; ma < 2; ++ma)
            #pragma unroll
            for (int rp = 0; rp < 2; ++rp) {
                int rl = wm * 32 + ma * 16 + rp * 8 + (lane >> 2);
                red[rl * 3 + 0] = dn[ma][rp];
                red[rl * 3 + 1] = x1[ma][rp];
                red[rl * 3 + 2] = x2[ma][rp];
            }
    }
    __syncthreads();
    if (wn == 0 && (lane & 3) == 0) {
        const int s = blockIdx.y;
        #pragma unroll
        for (int ma = 0; ma < 2; ++ma)
            #pragma unroll
            for (int rp = 0; rp < 2; ++rp) {
                int rl = wm * 32 + ma * 16 + rp * 8 + (lane >> 2);
                float a = dn[ma][rp] + red[rl * 3 + 0];
                float b = x1[ma][rp] + red[rl * 3 + 1];
                float cc = x2[ma][rp] + red[rl * 3 + 2];
                int g = bm + rl;
                if (CLS) {
                    g_pcl[((size_t)s * NR + g) * 3 + 0] = a;
                    g_pcl[((size_t)s * NR + g) * 3 + 1] = b;
                    g_pcl[((size_t)s * NR + g) * 3 + 2] = cc;
                } else {
                    g_pfg[((size_t)s * NR + g) * 2 + 0] = a;
                    g_pfg[((size_t)s * NR + g) * 2 + 1] = b;
                }
            }
    }
}

// ---------------- final deterministic reduction ----------------
__global__ void finalize_kernel(float* __restrict__ out) {
    __shared__ float red[256][4];
    int tid = threadIdx.x;
    float nfg = 0.0f, dfg = 0.0f, ncl = 0.0f, dcl = 0.0f;
    int nfgset = g_cnt[1];
    int nnon = g_cnt[0];
    for (int i = tid; i < NR; i += 256) {
        int l = g_lbl[i];
        if (l > 0) {
            float w = g_wgt[i];
            float dnv = 0.0f, nm = 0.0f;
            #pragma unroll
            for (int s = 0; s < NSPL; ++s) {
                dnv += g_pfg[((size_t)s * NR + i) * 2 + 0];
                nm  += g_pfg[((size_t)s * NR + i) * 2 + 1];
            }
            if (nfgset - 1 > 0) {
                float li = -logf((nm + 1e-8f) / (dnv + 1e-8f));
                nfg += li * w; dfg += w;
            }
            float dc = 0.0f, sp = 0.0f, np = 0.0f;
            #pragma unroll
            for (int s = 0; s < NSPL; ++s) {
                dc += g_pcl[((size_t)s * NR + i) * 3 + 0];
                sp += g_pcl[((size_t)s * NR + i) * 3 + 1];
                np += g_pcl[((size_t)s * NR + i) * 3 + 2];
            }
            if (np > 0.5f && (nnon - 1) > 0) {
                float li = -(5.0f * sp - np * logf(dc)) / np;
                ncl += li * w; dcl += w;
            }
        }
    }
    red[tid][0] = nfg; red[tid][1] = dfg; red[tid][2] = ncl; red[tid][3] = dcl;
    __syncthreads();
    for (int s = 128; s > 0; s >>= 1) {
        if (tid < s) {
            red[tid][0] += red[tid + s][0]; red[tid][1] += red[tid + s][1];
            red[tid][2] += red[tid + s][2]; red[tid][3] += red[tid + s][3];
        }
        __syncthreads();
    }
    if (tid == 0) {
        out[0] = red[0][0] / (red[0][1] + 1e-8f);
        out[1] = red[0][2] / (red[0][3] + 1e-12f);
    }
}

// ---------------- launch ----------------
extern "C" void kernel_launch(void* const* d_in, const int* in_sizes, int n_in,
                              void* d_out, int out_size) {
    const float* roi = (const float*)d_in[0];
    const int*   lab = (const int*)d_in[1];
    const float* iou = (const float*)d_in[2];
    const float* w1f = (const float*)d_in[3];
    const float* b1f = (const float*)d_in[4];
    const float* w2f = (const float*)d_in[5];
    const float* b2f = (const float*)d_in[6];
    const float* w1c = (const float*)d_in[7];
    const float* b1c = (const float*)d_in[8];
    const float* w2c = (const float*)d_in[9];
    const float* b2c = (const float*)d_in[10];

    __nv_bfloat16 *Xh, *Xl, *W1fh, *W1fl, *W1ch, *W1cl, *W2fh, *W2fl, *W2ch, *W2cl;
    __nv_bfloat16 *Hfh, *Hfl, *Hch, *Hcl, *Zfh, *Zfl, *Zch, *Zcl;
    float *Zf, *Zc;
    cudaGetSymbolAddress((void**)&Xh, g_Xh);     cudaGetSymbolAddress((void**)&Xl, g_Xl);
    cudaGetSymbolAddress((void**)&W1fh, g_W1fh); cudaGetSymbolAddress((void**)&W1fl, g_W1fl);
    cudaGetSymbolAddress((void**)&W1ch, g_W1ch); cudaGetSymbolAddress((void**)&W1cl, g_W1cl);
    cudaGetSymbolAddress((void**)&W2fh, g_W2fh); cudaGetSymbolAddress((void**)&W2fl, g_W2fl);
    cudaGetSymbolAddress((void**)&W2ch, g_W2ch); cudaGetSymbolAddress((void**)&W2cl, g_W2cl);
    cudaGetSymbolAddress((void**)&Hfh, g_Hfh);   cudaGetSymbolAddress((void**)&Hfl, g_Hfl);
    cudaGetSymbolAddress((void**)&Hch, g_Hch);   cudaGetSymbolAddress((void**)&Hcl, g_Hcl);
    cudaGetSymbolAddress((void**)&Zf, g_Zf);     cudaGetSymbolAddress((void**)&Zc, g_Zc);
    cudaGetSymbolAddress((void**)&Zfh, g_Zfh);   cudaGetSymbolAddress((void**)&Zfl, g_Zfl);
    cudaGetSymbolAddress((void**)&Zch, g_Zch);   cudaGetSymbolAddress((void**)&Zcl, g_Zcl);

    constexpr int SM_G128 = 2 * (2 * 128 * 144 + 2 * 128 * 144);  // 147456
    constexpr int SM_G64  = 2 * (2 * 128 * 144 + 2 * 64 * 144);   // 110592
    constexpr int SMEM_FG  = (NR / NSPL) * 4 + 6 * 128 * (FGDIM * 2 + 16);
    constexpr int SMEM_CLS = (NR / NSPL) * 4 + 6 * 128 * (CLDIM * 2 + 16);
    cudaFuncSetAttribute(mma_gemm<128, true>,  cudaFuncAttributeMaxDynamicSharedMemorySize, SM_G128);
    cudaFuncSetAttribute(mma_gemm<128, false>, cudaFuncAttributeMaxDynamicSharedMemorySize, SM_G128);
    cudaFuncSetAttribute(mma_gemm<64, false>,  cudaFuncAttributeMaxDynamicSharedMemorySize, SM_G64);
    cudaFuncSetAttribute(sim_mma_kernel<FGDIM, false>, cudaFuncAttributeMaxDynamicSharedMemorySize, SMEM_FG);
    cudaFuncSetAttribute(sim_mma_kernel<CLDIM, true>,  cudaFuncAttributeMaxDynamicSharedMemorySize, SMEM_CLS);

    zero_cnt_kernel<<<1, 1>>>();
    prep_kernel<<<NR / 256, 256>>>(lab, iou);

    // fp32 -> bf16 hi/lo conversions
    conv_hl_kernel<<<(NR * CD / 4 + 255) / 256, 256>>>(roi, Xh, Xl, NR * CD / 4);
    conv_hl_kernel<<<(HD * CD / 4 + 255) / 256, 256>>>(w1f, W1fh, W1fl, HD * CD / 4);
    conv_hl_kernel<<<(HD * CD / 4 + 255) / 256, 256>>>(w1c, W1ch, W1cl, HD * CD / 4);
    conv_hl_kernel<<<(FGDIM * HD / 4 + 255) / 256, 256>>>(w2f, W2fh, W2fl, FGDIM * HD / 4);
    conv_hl_kernel<<<(CLDIM * HD / 4 + 255) / 256, 256>>>(w2c, W2ch, W2cl, CLDIM * HD / 4);

    // layer 1 (both heads in one launch): H = relu(X @ W1^T + b1), bf16 hi/lo out
    mma_gemm<128, true><<<dim3(HD / 128, NR / 128, 2), 256, SM_G128>>>(
        Xh, Xl, Xh, Xl, W1fh, W1fl, W1ch, W1cl, b1f, b1c,
        Hfh, Hfl, Hch, Hcl, HD, CD);

    // layer 2: Z = H @ W2^T + b2 (fp32 out)
    mma_gemm<64, false><<<dim3(1, NR / 128, 1), 256, SM_G64>>>(
        Hfh, Hfl, Hfh, Hfl, W2fh, W2fl, W2fh, W2fl, b2f, b2f,
        Zf, nullptr, Zf, nullptr, FGDIM, HD);
    mma_gemm<128, false><<<dim3(1, NR / 128, 1), 256, SM_G128>>>(
        Hch, Hcl, Hch, Hcl, W2ch, W2cl, W2ch, W2cl, b2c, b2c,
        Zc, nullptr, Zc, nullptr, CLDIM, HD);

    // normalize + bf16 hi/lo split
    norm_conv_kernel<FGDIM><<<NR / 8, 256>>>(Zf, Zfh, Zfl);
    norm_conv_kernel<CLDIM><<<NR / 8, 256>>>(Zc, Zch, Zcl);

    // fused tensor-core sim + reductions
    sim_mma_kernel<FGDIM, false><<<dim3(64, NSPL), 256, SMEM_FG>>>();
    sim_mma_kernel<CLDIM, true><<<dim3(64, NSPL), 256, SMEM_CLS>>>();

    finalize_kernel<<<1, 256>>>((float*)d_out);
}

// round 5
// speedup vs baseline: 3.1196x; 1.2964x over previous
#include <cuda_runtime.h>
#include <cuda_bf16.h>
#include <math.h>
#include <stdint.h>

#define NR 8192
#define CD 1024
#define HD 256
#define FGDIM 64
#define CLDIM 128
#define NSPL_FG 4
#define NSPL_CLS 2

// ---------------- device scratch (no allocs allowed) ----------------
__device__ __nv_bfloat16 g_Xh[NR * CD];
__device__ __nv_bfloat16 g_Xl[NR * CD];
__device__ __nv_bfloat16 g_W1fh[HD * CD];
__device__ __nv_bfloat16 g_W1fl[HD * CD];
__device__ __nv_bfloat16 g_W1ch[HD * CD];
__device__ __nv_bfloat16 g_W1cl[HD * CD];
__device__ __nv_bfloat16 g_W2fh[FGDIM * HD];
__device__ __nv_bfloat16 g_W2fl[FGDIM * HD];
__device__ __nv_bfloat16 g_W2ch[CLDIM * HD];
__device__ __nv_bfloat16 g_W2cl[CLDIM * HD];
__device__ __nv_bfloat16 g_Hfh[NR * HD];
__device__ __nv_bfloat16 g_Hfl[NR * HD];
__device__ __nv_bfloat16 g_Hch[NR * HD];
__device__ __nv_bfloat16 g_Hcl[NR * HD];
__device__ float g_Zf[NR * FGDIM];
__device__ float g_Zc[NR * CLDIM];
__device__ __nv_bfloat16 g_Zfh[NR * FGDIM];
__device__ __nv_bfloat16 g_Zfl[NR * FGDIM];
__device__ __nv_bfloat16 g_Zch[NR * CLDIM];
__device__ __nv_bfloat16 g_Zcl[NR * CLDIM];
__device__ float g_pfg[NSPL_FG * NR * 2];    // per split, per row: denom, numer
__device__ float g_pcl[NSPL_CLS * NR];       // per split, per row: denom
__device__ float g_Sp[20 * 16 * CLDIM];      // per-class partial sums
__device__ float g_S[20 * CLDIM];            // per-class z sums
__device__ float g_sp[NR];                   // per-row sum_pos (CLS)
__device__ float g_eiif[NR];                 // per-row self exp (FG)
__device__ float g_eiic[NR];                 // per-row self exp (CLS)
__device__ int   g_lbl[NR];
__device__ float g_fgf[NR];                  // fg flag as float
__device__ float g_vld[NR];                  // ~ignore flag as float
__device__ float g_wgt[NR];
__device__ int   g_cnt[2];
__device__ int   g_hist[32];

// ---------------- helpers ----------------
__device__ __forceinline__ uint32_t smem_u32(const void* p) {
    uint32_t a;
    asm("{ .reg .u64 t; cvta.to.shared.u64 t, %1; cvt.u32.u64 %0, t; }" : "=r"(a) : "l"(p));
    return a;
}

#define LDSM4(r, addr) \
    asm volatile("ldmatrix.sync.aligned.m8n8.x4.shared.b16 {%0,%1,%2,%3}, [%4];" \
        : "=r"((r)[0]), "=r"((r)[1]), "=r"((r)[2]), "=r"((r)[3]) : "r"(addr))

#define MMA16816(d, a, b0, b1) \
    asm volatile("mma.sync.aligned.m16n8k16.row.col.f32.bf16.bf16.f32 " \
        "{%0,%1,%2,%3},{%4,%5,%6,%7},{%8,%9},{%0,%1,%2,%3};" \
        : "+f"((d)[0]), "+f"((d)[1]), "+f"((d)[2]), "+f"((d)[3]) \
        : "r"((a)[0]), "r"((a)[1]), "r"((a)[2]), "r"((a)[3]), "r"(b0), "r"(b1))

// ---------------- small kernels ----------------
__global__ void zero_cnt_kernel() {
    int t = threadIdx.x;
    if (t < 2) g_cnt[t] = 0;
    if (t < 32) g_hist[t] = 0;
}

__global__ void prep_kernel(const int* __restrict__ lraw, const float* __restrict__ ious) {
    int i = blockIdx.x * blockDim.x + threadIdx.x;
    bool is64 = true;
    #pragma unroll 1
    for (int p = 0; p < 32; ++p) {
        int lo = lraw[2 * p], hi = lraw[2 * p + 1];
        bool ok = (hi == 0 && lo >= 0) || (hi == -1 && lo < 0);
        if (!ok) { is64 = false; break; }
    }
    int l = is64 ? (int)(((const long long*)lraw)[i]) : lraw[i];
    g_lbl[i] = l;
    g_fgf[i] = (l > 0) ? 1.0f : 0.0f;
    g_vld[i] = (l != -1) ? 1.0f : 0.0f;
    float u = ious[i];
    g_wgt[i] = (u > 0.5f) ? u : 0.0f;

    __shared__ int s0, s1, sh[32];
    if (threadIdx.x == 0) { s0 = 0; s1 = 0; }
    if (threadIdx.x < 32) sh[threadIdx.x] = 0;
    __syncthreads();
    if (l != -1) atomicAdd(&s0, 1);
    if (l > 0)   atomicAdd(&s1, 1);
    atomicAdd(&sh[l + 1], 1);
    __syncthreads();
    if (threadIdx.x == 0) { atomicAdd(&g_cnt[0], s0); atomicAdd(&g_cnt[1], s1); }
    if (threadIdx.x < 32 && sh[threadIdx.x]) atomicAdd(&g_hist[threadIdx.x], sh[threadIdx.x]);
}

// ---------------- fp32 -> bf16 hi/lo split conversion ----------------
__global__ void conv_hl_kernel(const float* __restrict__ s,
                               __nv_bfloat16* __restrict__ h,
                               __nv_bfloat16* __restrict__ l, int n4) {
    int i = blockIdx.x * blockDim.x + threadIdx.x;
    if (i >= n4) return;
    float4 v = ((const float4*)s)[i];
    __nv_bfloat162 h0, h1, l0, l1;
    h0.x = __float2bfloat16(v.x); h0.y = __float2bfloat16(v.y);
    h1.x = __float2bfloat16(v.z); h1.y = __float2bfloat16(v.w);
    l0.x = __float2bfloat16(v.x - __bfloat162float(h0.x));
    l0.y = __float2bfloat16(v.y - __bfloat162float(h0.y));
    l1.x = __float2bfloat16(v.z - __bfloat162float(h1.x));
    l1.y = __float2bfloat16(v.w - __bfloat162float(h1.y));
    ((__nv_bfloat162*)h)[i * 2] = h0; ((__nv_bfloat162*)h)[i * 2 + 1] = h1;
    ((__nv_bfloat162*)l)[i * 2] = l0; ((__nv_bfloat162*)l)[i * 2 + 1] = l1;
}

// ---------------- cp.async bf16 tile loader (BK=64, padded stride 144B) ----------------
__device__ __forceinline__ void ld_tile64(uint32_t dst, const __nv_bfloat16* __restrict__ src,
                                          int rows, int K, int tid) {
    #pragma unroll 4
    for (int i = tid; i < rows * 8; i += 256) {
        int r = i >> 3, c = i & 7;
        asm volatile("cp.async.cg.shared.global [%0], [%1], 16;"
                     :: "r"(dst + r * 144 + c * 16), "l"(src + (size_t)r * K + c * 8) : "memory");
    }
}

// ---------------- MMA GEMM (MLP): 3-chain, unchanged from round 4 ----------------
template<int BN, bool RELU_SPLIT>
__global__ __launch_bounds__(256) void mma_gemm(
    const __nv_bfloat16* __restrict__ Ah0, const __nv_bfloat16* __restrict__ Al0,
    const __nv_bfloat16* __restrict__ Ah1, const __nv_bfloat16* __restrict__ Al1,
    const __nv_bfloat16* __restrict__ Wh0, const __nv_bfloat16* __restrict__ Wl0,
    const __nv_bfloat16* __restrict__ Wh1, const __nv_bfloat16* __restrict__ Wl1,
    const float* __restrict__ bias0, const float* __restrict__ bias1,
    void* __restrict__ o0a, void* __restrict__ o0b,
    void* __restrict__ o1a, void* __restrict__ o1b,
    int N, int K) {
    constexpr int SA = 144;
    constexpr int ATS = 128 * SA;
    constexpr int BTS = BN * SA;
    constexpr int STG = 2 * ATS + 2 * BTS;
    constexpr int NG = BN / 32;
    constexpr int NF = 2 * NG;

    extern __shared__ char smem[];
    uint32_t sb = smem_u32(smem);
    const int tid = threadIdx.x, wid = tid >> 5, lane = tid & 31;
    const int wm = wid & 3, wn = wid >> 2;
    const int z = blockIdx.z;
    const int bm = blockIdx.y * 128, bn = blockIdx.x * BN;

    const __nv_bfloat16* Ah = z ? Ah1 : Ah0;
    const __nv_bfloat16* Al = z ? Al1 : Al0;
    const __nv_bfloat16* Wh = z ? Wh1 : Wh0;
    const __nv_bfloat16* Wl = z ? Wl1 : Wl0;
    const float* bias = z ? bias1 : bias0;

    const int KC = K >> 6;

    ld_tile64(sb, Ah + (size_t)bm * K, 128, K, tid);
    ld_tile64(sb + ATS, Al + (size_t)bm * K, 128, K, tid);
    ld_tile64(sb + 2 * ATS, Wh + (size_t)bn * K, BN, K, tid);
    ld_tile64(sb + 2 * ATS + BTS, Wl + (size_t)bn * K, BN, K, tid);
    asm volatile("cp.async.commit_group;" ::: "memory");

    float acc[2][NF][4];
    #pragma unroll
    for (int ma = 0; ma < 2; ++ma)
        #pragma unroll
        for (int nf = 0; nf < NF; ++nf)
            #pragma unroll
            for (int e = 0; e < 4; ++e) acc[ma][nf][e] = 0.0f;

    const uint32_t a_off = (uint32_t)((wm * 32 + (lane & 15)) * SA + (lane >> 4) * 16);
    const uint32_t b_off = (uint32_t)((wn * (BN / 2) + ((lane >> 4) << 3) + (lane & 7)) * SA + ((lane >> 3) & 1) * 16);

    for (int kc = 0; kc < KC; ++kc) {
        const uint32_t cur = sb + (kc & 1) * STG;
        if (kc + 1 < KC) {
            const uint32_t nxt = sb + ((kc + 1) & 1) * STG;
            const int ko = (kc + 1) * 64;
            ld_tile64(nxt, Ah + (size_t)bm * K + ko, 128, K, tid);
            ld_tile64(nxt + ATS, Al + (size_t)bm * K + ko, 128, K, tid);
            ld_tile64(nxt + 2 * ATS, Wh + (size_t)bn * K + ko, BN, K, tid);
            ld_tile64(nxt + 2 * ATS + BTS, Wl + (size_t)bn * K + ko, BN, K, tid);
            asm volatile("cp.async.commit_group;" ::: "memory");
            asm volatile("cp.async.wait_group 1;" ::: "memory");
        } else {
            asm volatile("cp.async.wait_group 0;" ::: "memory");
        }
        __syncthreads();

        #pragma unroll
        for (int ks = 0; ks < 4; ++ks) {
            const uint32_t kb = ks * 32;
            uint32_t a_h[2][4], a_l[2][4], b_h[NG][4], b_l[NG][4];
            #pragma unroll
            for (int ma = 0; ma < 2; ++ma) {
                LDSM4(a_h[ma], cur + a_off + ma * 16 * SA + kb);
                LDSM4(a_l[ma], cur + ATS + a_off + ma * 16 * SA + kb);
            }
            #pragma unroll
            for (int g = 0; g < NG; ++g) {
                LDSM4(b_h[g], cur + 2 * ATS + b_off + g * 16 * SA + kb);
                LDSM4(b_l[g], cur + 2 * ATS + BTS + b_off + g * 16 * SA + kb);
            }
            #pragma unroll
            for (int ma = 0; ma < 2; ++ma)
                #pragma unroll
                for (int g = 0; g < NG; ++g) {
                    MMA16816(acc[ma][2 * g],     a_h[ma], b_h[g][0], b_h[g][1]);
                    MMA16816(acc[ma][2 * g + 1], a_h[ma], b_h[g][2], b_h[g][3]);
                    MMA16816(acc[ma][2 * g],     a_h[ma], b_l[g][0], b_l[g][1]);
                    MMA16816(acc[ma][2 * g + 1], a_h[ma], b_l[g][2], b_l[g][3]);
                    MMA16816(acc[ma][2 * g],     a_l[ma], b_h[g][0], b_h[g][1]);
                    MMA16816(acc[ma][2 * g + 1], a_l[ma], b_h[g][2], b_h[g][3]);
                }
        }
        __syncthreads();
    }

    #pragma unroll
    for (int ma = 0; ma < 2; ++ma)
        #pragma unroll
        for (int nf = 0; nf < NF; ++nf)
            #pragma unroll
            for (int rp = 0; rp < 2; ++rp) {
                const int r = bm + wm * 32 + ma * 16 + rp * 8 + (lane >> 2);
                const int c = bn + wn * (BN / 2) + nf * 8 + (lane & 3) * 2;
                float2 bb = *(const float2*)(bias + c);
                float v0 = acc[ma][nf][rp * 2 + 0] + bb.x;
                float v1 = acc[ma][nf][rp * 2 + 1] + bb.y;
                if (RELU_SPLIT) {
                    v0 = fmaxf(v0, 0.0f); v1 = fmaxf(v1, 0.0f);
                    __nv_bfloat16* oh = (__nv_bfloat16*)(z ? o1a : o0a);
                    __nv_bfloat16* ol = (__nv_bfloat16*)(z ? o1b : o0b);
                    __nv_bfloat162 hv, lv;
                    hv.x = __float2bfloat16(v0); hv.y = __float2bfloat16(v1);
                    lv.x = __float2bfloat16(v0 - __bfloat162float(hv.x));
                    lv.y = __float2bfloat16(v1 - __bfloat162float(hv.y));
                    *(__nv_bfloat162*)(oh + (size_t)r * N + c) = hv;
                    *(__nv_bfloat162*)(ol + (size_t)r * N + c) = lv;
                } else {
                    float* of = (float*)(z ? o1a : o0a);
                    float2 ov; ov.x = v0; ov.y = v1;
                    *(float2*)(of + (size_t)r * N + c) = ov;
                }
            }
}

// ---------------- row L2-normalize + bf16 hi/lo split + fp32 writeback ----------------
template<int KD>
__global__ void norm_conv_kernel(float* __restrict__ Z,
                                 __nv_bfloat16* __restrict__ Oh,
                                 __nv_bfloat16* __restrict__ Ol) {
    int row = blockIdx.x * 8 + (threadIdx.x >> 5);
    int lane = threadIdx.x & 31;
    float ss = 0.0f;
    #pragma unroll
    for (int c = lane; c < KD; c += 32) { float v = Z[(size_t)row * KD + c]; ss += v * v; }
    #pragma unroll
    for (int o = 16; o; o >>= 1) ss += __shfl_xor_sync(0xffffffffu, ss, o);
    float inv = 1.0f / fmaxf(sqrtf(ss), 1e-8f);
    #pragma unroll
    for (int c = lane; c < KD; c += 32) {
        float v = Z[(size_t)row * KD + c] * inv;
        Z[(size_t)row * KD + c] = v;
        __nv_bfloat16 h = __float2bfloat16(v);
        Oh[(size_t)row * KD + c] = h;
        Ol[(size_t)row * KD + c] = __float2bfloat16(v - __bfloat162float(h));
    }
}

// ---------------- per-class z sums (for CLS sum_pos factorization) ----------------
__global__ void class_sum1_kernel() {     // grid (20, 16), block CLDIM
    const int c = blockIdx.x + 1;
    const int d = threadIdx.x;
    const int i0 = blockIdx.y * (NR / 16);
    float s = 0.0f;
    for (int i = i0; i < i0 + NR / 16; ++i)
        if (g_lbl[i] == c) s += g_Zc[(size_t)i * CLDIM + d];
    g_Sp[(blockIdx.x * 16 + blockIdx.y) * CLDIM + d] = s;
}
__global__ void class_sum2_kernel() {     // grid 20, block CLDIM
    float s = 0.0f;
    #pragma unroll
    for (int g = 0; g < 16; ++g) s += g_Sp[(blockIdx.x * 16 + g) * CLDIM + threadIdx.x];
    g_S[blockIdx.x * CLDIM + threadIdx.x] = s;
}

// ---------------- FMA-only exp(5x), degree-4 (no MUFU) ----------------
__device__ __forceinline__ float fexp5(float x) {
    const float KE = 7.2134752044448169f;
    const float SH = 12582912.0f;
    float z = fmaf(x, KE, SH);
    int   ei = __float_as_int(z);
    float r = z - SH;
    float f = fmaf(x, KE, -r);
    float p = 9.6181291076284771e-3f;
    p = fmaf(p, f, 5.5504108664821580e-2f);
    p = fmaf(p, f, 2.4022650695910071e-1f);
    p = fmaf(p, f, 6.9314718055994531e-1f);
    p = fmaf(p, f, 1.0f);
    return p * __int_as_float((ei - 0x4B400000 + 127) << 23);
}

// ---------------- per-row diag exps + CLS sum_pos (warp per row) ----------------
__global__ void row_sp_kernel() {
    int row = blockIdx.x * 8 + (threadIdx.x >> 5);
    int lane = threadIdx.x & 31;
    // FG: d_ii = dot(zf, h(zf))
    float df = 0.0f;
    #pragma unroll
    for (int c = lane; c < FGDIM; c += 32)
        df += g_Zf[(size_t)row * FGDIM + c] * __bfloat162float(g_Zfh[(size_t)row * FGDIM + c]);
    // CLS: d_ii, ||z||^2, dot(z, S_li)
    int l = g_lbl[row];
    const float* S = g_S + (l > 0 ? (l - 1) : 0) * CLDIM;
    float dc = 0.0f, ss = 0.0f, sd = 0.0f;
    #pragma unroll
    for (int c = lane; c < CLDIM; c += 32) {
        float zv = g_Zc[(size_t)row * CLDIM + c];
        dc += zv * __bfloat162float(g_Zch[(size_t)row * CLDIM + c]);
        ss += zv * zv;
        sd += zv * S[c];
    }
    #pragma unroll
    for (int o = 16; o; o >>= 1) {
        df += __shfl_xor_sync(0xffffffffu, df, o);
        dc += __shfl_xor_sync(0xffffffffu, dc, o);
        ss += __shfl_xor_sync(0xffffffffu, ss, o);
        sd += __shfl_xor_sync(0xffffffffu, sd, o);
    }
    if (lane == 0) {
        g_eiif[row] = fexp5(df);
        g_eiic[row] = fexp5(dc);
        g_sp[row] = 5.0f * (sd - ss);
    }
}

// ---------------- cp.async tile loader for sim (full K resident) ----------------
template<int KD>
__device__ __forceinline__ void load_tile(uint32_t dst, const __nv_bfloat16* __restrict__ src, int tid) {
    constexpr int CPR = KD / 8;
    constexpr int SA = KD * 2 + 16;
    #pragma unroll
    for (int i = tid; i < 128 * CPR; i += 256) {
        int r = i / CPR, c = i % CPR;
        asm volatile("cp.async.cg.shared.global [%0], [%1], 16;"
                     :: "r"(dst + r * SA + c * 16), "l"(src + (size_t)r * KD + c * 8) : "memory");
    }
}

// ---------------- warp-MMA fused sim kernel (2-chain, flag epilogue) ----------------
// D = z_A . h_B^T = Ah*Bh^T + Al*Bh^T. Epilogue: e = exp(5v); dn += e*?; x1 += e*flag.
// Diagonal included here, subtracted in finalize.
template<int KD, bool CLS, int NSPLT>
__global__ __launch_bounds__(256) void sim_mma_kernel() {
    constexpr int SA = KD * 2 + 16;
    constexpr int TSZ = 128 * SA;
    constexpr int SLAB = NR / NSPLT;
    constexpr int TCOLS = SLAB / 128;
    constexpr int KSTEPS = KD / 16;
    constexpr int A_HI = SLAB * 4;
    constexpr int A_LO = A_HI + TSZ;
    constexpr int B_OFF = A_LO + TSZ;           // 2 buffers, hi only

    extern __shared__ char smem[];
    float* slab = (float*)smem;
    uint32_t sb = smem_u32(smem);
    const int tid = threadIdx.x, wid = tid >> 5, lane = tid & 31;
    const int wm = wid & 3, wn = wid >> 4 ? 1 : (wid >> 2);   // wid>>2 in {0,1}
    const int bm = blockIdx.x * 128;
    const int c0 = blockIdx.y * SLAB;
    const __nv_bfloat16* Zh = CLS ? g_Zch : g_Zfh;
    const __nv_bfloat16* Zl = CLS ? g_Zcl : g_Zfl;
    const float* flg = CLS ? g_vld : g_fgf;

    for (int i = tid; i < SLAB; i += 256)
        slab[i] = flg[c0 + i];

    load_tile<KD>(sb + A_HI, Zh + (size_t)bm * KD, tid);
    load_tile<KD>(sb + A_LO, Zl + (size_t)bm * KD, tid);
    load_tile<KD>(sb + B_OFF, Zh + (size_t)c0 * KD, tid);
    asm volatile("cp.async.commit_group;" ::: "memory");

    float dn[2][2] = {{0, 0}, {0, 0}};
    float x1[2][2] = {{0, 0}, {0, 0}};

    const uint32_t a_off = (uint32_t)((wm * 32 + (lane & 15)) * SA + (lane >> 4) * 16);
    const uint32_t b_off = (uint32_t)((wn * 64 + ((lane >> 4) << 3) + (lane & 7)) * SA + ((lane >> 3) & 1) * 16);

    float acc[2][8][4];
    #pragma unroll
    for (int ma = 0; ma < 2; ++ma)
        #pragma unroll
        for (int na = 0; na < 8; ++na)
            #pragma unroll
            for (int e = 0; e < 4; ++e) acc[ma][na][e] = 0.0f;

    asm volatile("cp.async.wait_group 0;" ::: "memory");
    __syncthreads();

    for (int t = 0; t < TCOLS; ++t) {
        const uint32_t bcur = sb + B_OFF + (t & 1) * TSZ;
        if (t + 1 < TCOLS) {
            load_tile<KD>(sb + B_OFF + ((t + 1) & 1) * TSZ,
                          Zh + (size_t)(c0 + (t + 1) * 128) * KD, tid);
            asm volatile("cp.async.commit_group;" ::: "memory");
        }

        #pragma unroll
        for (int ks = 0; ks < KSTEPS; ++ks) {
            uint32_t a_h[2][4], a_l[2][4], b_h[4][4];
            const uint32_t kb = ks * 32;
            #pragma unroll
            for (int ma = 0; ma < 2; ++ma) {
                LDSM4(a_h[ma], sb + A_HI + a_off + ma * 16 * SA + kb);
                LDSM4(a_l[ma], sb + A_LO + a_off + ma * 16 * SA + kb);
            }
            #pragma unroll
            for (int g = 0; g < 4; ++g)
                LDSM4(b_h[g], bcur + b_off + g * 16 * SA + kb);
            #pragma unroll
            for (int ma = 0; ma < 2; ++ma)
                #pragma unroll
                for (int g = 0; g < 4; ++g) {
                    MMA16816(acc[ma][2 * g],     a_h[ma], b_h[g][0], b_h[g][1]);
                    MMA16816(acc[ma][2 * g + 1], a_h[ma], b_h[g][2], b_h[g][3]);
                    MMA16816(acc[ma][2 * g],     a_l[ma], b_h[g][0], b_h[g][1]);
                    MMA16816(acc[ma][2 * g + 1], a_l[ma], b_h[g][2], b_h[g][3]);
                }
        }

        const int tb = t * 128;
        #pragma unroll
        for (int ma = 0; ma < 2; ++ma)
            #pragma unroll
            for (int na = 0; na < 8; ++na) {
                const int cA = wn * 64 + na * 8 + (lane & 3) * 2;
                const float2 lp = *(const float2*)(slab + tb + cA);
                float* c = acc[ma][na];
                #pragma unroll
                for (int e = 0; e < 4; ++e) {
                    const float ex = fexp5(c[e]);
                    const float fl = (e & 1) ? lp.y : lp.x;
                    const int rp = e >> 1;
                    if (CLS) {
                        dn[ma][rp] = fmaf(ex, fl, dn[ma][rp]);
                    } else {
                        dn[ma][rp] += ex;
                        x1[ma][rp] = fmaf(ex, fl, x1[ma][rp]);
                    }
                    c[e] = 0.0f;
                }
            }

        if (t + 1 < TCOLS) {
            asm volatile("cp.async.wait_group 0;" ::: "memory");
        }
        __syncthreads();
    }

    // quad reduction (lanes sharing rows)
    #pragma unroll
    for (int ma = 0; ma < 2; ++ma)
        #pragma unroll
        for (int rp = 0; rp < 2; ++rp) {
            #pragma unroll
            for (int o = 1; o <= 2; o <<= 1) {
                dn[ma][rp] += __shfl_xor_sync(0xffffffffu, dn[ma][rp], o);
                if (!CLS) x1[ma][rp] += __shfl_xor_sync(0xffffffffu, x1[ma][rp], o);
            }
        }

    float* red = (float*)smem;
    __syncthreads();
    if (wn == 1 && (lane & 3) == 0) {
        #pragma unroll
        for (int ma = 0; ma < 2; ++ma)
            #pragma unroll
            for (int rp = 0; rp < 2; ++rp) {
                int rl = wm * 32 + ma * 16 + rp * 8 + (lane >> 2);
                red[rl * 2 + 0] = dn[ma][rp];
                red[rl * 2 + 1] = x1[ma][rp];
            }
    }
    __syncthreads();
    if (wn == 0 && (lane & 3) == 0) {
        const int s = blockIdx.y;
        #pragma unroll
        for (int ma = 0; ma < 2; ++ma)
            #pragma unroll
            for (int rp = 0; rp < 2; ++rp) {
                int rl = wm * 32 + ma * 16 + rp * 8 + (lane >> 2);
                float a = dn[ma][rp] + red[rl * 2 + 0];
                int g = bm + rl;
                if (CLS) {
                    g_pcl[(size_t)s * NR + g] = a;
                } else {
                    float b = x1[ma][rp] + red[rl * 2 + 1];
                    g_pfg[((size_t)s * NR + g) * 2 + 0] = a;
                    g_pfg[((size_t)s * NR + g) * 2 + 1] = b;
                }
            }
    }
}

// ---------------- final deterministic reduction ----------------
__global__ void finalize_kernel(float* __restrict__ out) {
    __shared__ float red[256][4];
    int tid = threadIdx.x;
    float nfg = 0.0f, dfg = 0.0f, ncl = 0.0f, dcl = 0.0f;
    int nfgset = g_cnt[1];
    int nnon = g_cnt[0];
    for (int i = tid; i < NR; i += 256) {
        int l = g_lbl[i];
        if (l > 0) {
            float w = g_wgt[i];
            float dnv = 0.0f, nm = 0.0f;
            #pragma unroll
            for (int s = 0; s < NSPL_FG; ++s) {
                dnv += g_pfg[((size_t)s * NR + i) * 2 + 0];
                nm  += g_pfg[((size_t)s * NR + i) * 2 + 1];
            }
            float ef = g_eiif[i];
            dnv -= ef; nm -= ef;
            if (nfgset - 1 > 0) {
                float li = -logf((nm + 1e-8f) / (dnv + 1e-8f));
                nfg += li * w; dfg += w;
            }
            float dc = 0.0f;
            #pragma unroll
            for (int s = 0; s < NSPL_CLS; ++s)
                dc += g_pcl[(size_t)s * NR + i];
            dc -= g_eiic[i];
            float np = (float)(g_hist[l + 1] - 1);
            if (np > 0.5f && (nnon - 1) > 0) {
                float li = -(g_sp[i] - np * logf(dc)) / np;
                ncl += li * w; dcl += w;
            }
        }
    }
    red[tid][0] = nfg; red[tid][1] = dfg; red[tid][2] = ncl; red[tid][3] = dcl;
    __syncthreads();
    for (int s = 128; s > 0; s >>= 1) {
        if (tid < s) {
            red[tid][0] += red[tid + s][0]; red[tid][1] += red[tid + s][1];
            red[tid][2] += red[tid + s][2]; red[tid][3] += red[tid + s][3];
        }
        __syncthreads();
    }
    if (tid == 0) {
        out[0] = red[0][0] / (red[0][1] + 1e-8f);
        out[1] = red[0][2] / (red[0][3] + 1e-12f);
    }
}

// ---------------- launch ----------------
extern "C" void kernel_launch(void* const* d_in, const int* in_sizes, int n_in,
                              void* d_out, int out_size) {
    const float* roi = (const float*)d_in[0];
    const int*   lab = (const int*)d_in[1];
    const float* iou = (const float*)d_in[2];
    const float* w1f = (const float*)d_in[3];
    const float* b1f = (const float*)d_in[4];
    const float* w2f = (const float*)d_in[5];
    const float* b2f = (const float*)d_in[6];
    const float* w1c = (const float*)d_in[7];
    const float* b1c = (const float*)d_in[8];
    const float* w2c = (const float*)d_in[9];
    const float* b2c = (const float*)d_in[10];

    __nv_bfloat16 *Xh, *Xl, *W1fh, *W1fl, *W1ch, *W1cl, *W2fh, *W2fl, *W2ch, *W2cl;
    __nv_bfloat16 *Hfh, *Hfl, *Hch, *Hcl, *Zfh, *Zfl, *Zch, *Zcl;
    float *Zf, *Zc;
    cudaGetSymbolAddress((void**)&Xh, g_Xh);     cudaGetSymbolAddress((void**)&Xl, g_Xl);
    cudaGetSymbolAddress((void**)&W1fh, g_W1fh); cudaGetSymbolAddress((void**)&W1fl, g_W1fl);
    cudaGetSymbolAddress((void**)&W1ch, g_W1ch); cudaGetSymbolAddress((void**)&W1cl, g_W1cl);
    cudaGetSymbolAddress((void**)&W2fh, g_W2fh); cudaGetSymbolAddress((void**)&W2fl, g_W2fl);
    cudaGetSymbolAddress((void**)&W2ch, g_W2ch); cudaGetSymbolAddress((void**)&W2cl, g_W2cl);
    cudaGetSymbolAddress((void**)&Hfh, g_Hfh);   cudaGetSymbolAddress((void**)&Hfl, g_Hfl);
    cudaGetSymbolAddress((void**)&Hch, g_Hch);   cudaGetSymbolAddress((void**)&Hcl, g_Hcl);
    cudaGetSymbolAddress((void**)&Zf, g_Zf);     cudaGetSymbolAddress((void**)&Zc, g_Zc);
    cudaGetSymbolAddress((void**)&Zfh, g_Zfh);   cudaGetSymbolAddress((void**)&Zfl, g_Zfl);
    cudaGetSymbolAddress((void**)&Zch, g_Zch);   cudaGetSymbolAddress((void**)&Zcl, g_Zcl);

    constexpr int SM_G128 = 2 * (2 * 128 * 144 + 2 * 128 * 144);
    constexpr int SM_G64  = 2 * (2 * 128 * 144 + 2 * 64 * 144);
    // sim: slab + A(hi,lo) + B(hi) x2 buffers
    constexpr int SMEM_FG  = (NR / NSPL_FG) * 4 + 4 * 128 * (FGDIM * 2 + 16);   // 81920
    constexpr int SMEM_CLS = (NR / NSPL_CLS) * 4 + 4 * 128 * (CLDIM * 2 + 16);  // 155648
    cudaFuncSetAttribute(mma_gemm<128, true>,  cudaFuncAttributeMaxDynamicSharedMemorySize, SM_G128);
    cudaFuncSetAttribute(mma_gemm<128, false>, cudaFuncAttributeMaxDynamicSharedMemorySize, SM_G128);
    cudaFuncSetAttribute(mma_gemm<64, false>,  cudaFuncAttributeMaxDynamicSharedMemorySize, SM_G64);
    cudaFuncSetAttribute(sim_mma_kernel<FGDIM, false, NSPL_FG>, cudaFuncAttributeMaxDynamicSharedMemorySize, SMEM_FG);
    cudaFuncSetAttribute(sim_mma_kernel<CLDIM, true, NSPL_CLS>, cudaFuncAttributeMaxDynamicSharedMemorySize, SMEM_CLS);

    zero_cnt_kernel<<<1, 32>>>();
    prep_kernel<<<NR / 256, 256>>>(lab, iou);

    conv_hl_kernel<<<(NR * CD / 4 + 255) / 256, 256>>>(roi, Xh, Xl, NR * CD / 4);
    conv_hl_kernel<<<(HD * CD / 4 + 255) / 256, 256>>>(w1f, W1fh, W1fl, HD * CD / 4);
    conv_hl_kernel<<<(HD * CD / 4 + 255) / 256, 256>>>(w1c, W1ch, W1cl, HD * CD / 4);
    conv_hl_kernel<<<(FGDIM * HD / 4 + 255) / 256, 256>>>(w2f, W2fh, W2fl, FGDIM * HD / 4);
    conv_hl_kernel<<<(CLDIM * HD / 4 + 255) / 256, 256>>>(w2c, W2ch, W2cl, CLDIM * HD / 4);

    mma_gemm<128, true><<<dim3(HD / 128, NR / 128, 2), 256, SM_G128>>>(
        Xh, Xl, Xh, Xl, W1fh, W1fl, W1ch, W1cl, b1f, b1c,
        Hfh, Hfl, Hch, Hcl, HD, CD);

    mma_gemm<64, false><<<dim3(1, NR / 128, 1), 256, SM_G64>>>(
        Hfh, Hfl, Hfh, Hfl, W2fh, W2fl, W2fh, W2fl, b2f, b2f,
        Zf, nullptr, Zf, nullptr, FGDIM, HD);
    mma_gemm<128, false><<<dim3(1, NR / 128, 1), 256, SM_G128>>>(
        Hch, Hcl, Hch, Hcl, W2ch, W2cl, W2ch, W2cl, b2c, b2c,
        Zc, nullptr, Zc, nullptr, CLDIM, HD);

    norm_conv_kernel<FGDIM><<<NR / 8, 256>>>(Zf, Zfh, Zfl);
    norm_conv_kernel<CLDIM><<<NR / 8, 256>>>(Zc, Zch, Zcl);

    class_sum1_kernel<<<dim3(20, 16), CLDIM>>>();
    class_sum2_kernel<<<20, CLDIM>>>();
    row_sp_kernel<<<NR / 8, 256>>>();

    sim_mma_kernel<FGDIM, false, NSPL_FG><<<dim3(64, NSPL_FG), 256, SMEM_FG>>>();
    sim_mma_kernel<CLDIM, true, NSPL_CLS><<<dim3(64, NSPL_CLS), 256, SMEM_CLS>>>();

    finalize_kernel<<<1, 256>>>((float*)d_out);
}

// round 6
// speedup vs baseline: 3.4161x; 1.0950x over previous
#include <cuda_runtime.h>
#include <cuda_bf16.h>
#include <math.h>
#include <stdint.h>

#define NR 8192
#define CD 1024
#define HD 256
#define FGDIM 64
#define CLDIM 128
#define NSPL_FG 4
#define NSPL_CLS 2

// ---------------- device scratch (no allocs allowed) ----------------
__device__ __nv_bfloat16 g_Xh[NR * CD];
__device__ __nv_bfloat16 g_Xl[NR * CD];
__device__ __nv_bfloat16 g_W1fh[HD * CD];
__device__ __nv_bfloat16 g_W1fl[HD * CD];
__device__ __nv_bfloat16 g_W1ch[HD * CD];
__device__ __nv_bfloat16 g_W1cl[HD * CD];
__device__ __nv_bfloat16 g_W2fh[FGDIM * HD];
__device__ __nv_bfloat16 g_W2fl[FGDIM * HD];
__device__ __nv_bfloat16 g_W2ch[CLDIM * HD];
__device__ __nv_bfloat16 g_W2cl[CLDIM * HD];
__device__ __nv_bfloat16 g_Hfh[NR * HD];
__device__ __nv_bfloat16 g_Hfl[NR * HD];
__device__ __nv_bfloat16 g_Hch[NR * HD];
__device__ __nv_bfloat16 g_Hcl[NR * HD];
__device__ float g_Zf[NR * FGDIM];
__device__ float g_Zc[NR * CLDIM];
__device__ __nv_bfloat16 g_Zfh[NR * FGDIM];
__device__ __nv_bfloat16 g_Zfl[NR * FGDIM];
__device__ __nv_bfloat16 g_Zch[NR * CLDIM];
__device__ __nv_bfloat16 g_Zcl[NR * CLDIM];
__device__ float g_pfg[NSPL_FG * NR * 2];    // per split, per row: denom, numer
__device__ float g_pcl[NSPL_CLS * NR];       // per split, per row: denom
__device__ float g_Sp[20 * 16 * CLDIM];      // per-class partial sums
__device__ float g_S[20 * CLDIM];            // per-class z sums
__device__ float g_sp[NR];                   // per-row sum_pos (CLS)
__device__ float g_eiif[NR];                 // per-row self exp (FG)
__device__ float g_eiic[NR];                 // per-row self exp (CLS)
__device__ int   g_lbl[NR];
__device__ float g_fgf[NR];                  // fg flag as float
__device__ float g_vld[NR];                  // ~ignore flag as float
__device__ float g_wgt[NR];

// ---------------- helpers ----------------
__device__ __forceinline__ uint32_t smem_u32(const void* p) {
    uint32_t a;
    asm("{ .reg .u64 t; cvta.to.shared.u64 t, %1; cvt.u32.u64 %0, t; }" : "=r"(a) : "l"(p));
    return a;
}

#define LDSM4(r, addr) \
    asm volatile("ldmatrix.sync.aligned.m8n8.x4.shared.b16 {%0,%1,%2,%3}, [%4];" \
        : "=r"((r)[0]), "=r"((r)[1]), "=r"((r)[2]), "=r"((r)[3]) : "r"(addr))

#define MMA16816(d, a, b0, b1) \
    asm volatile("mma.sync.aligned.m16n8k16.row.col.f32.bf16.bf16.f32 " \
        "{%0,%1,%2,%3},{%4,%5,%6,%7},{%8,%9},{%0,%1,%2,%3};" \
        : "+f"((d)[0]), "+f"((d)[1]), "+f"((d)[2]), "+f"((d)[3]) \
        : "r"((a)[0]), "r"((a)[1]), "r"((a)[2]), "r"((a)[3]), "r"(b0), "r"(b1))

// ---------------- packed f32x2 ops (sm_100+ base ISA) ----------------
__device__ __forceinline__ uint64_t pk2(float a, float b) {
    uint64_t r; asm("mov.b64 %0, {%1, %2};" : "=l"(r) : "f"(a), "f"(b)); return r;
}
__device__ __forceinline__ void upk2(uint64_t v, float& a, float& b) {
    asm("mov.b64 {%0, %1}, %2;" : "=f"(a), "=f"(b) : "l"(v));
}
__device__ __forceinline__ uint64_t fma2(uint64_t a, uint64_t b, uint64_t c) {
    uint64_t d; asm("fma.rn.f32x2 %0, %1, %2, %3;" : "=l"(d) : "l"(a), "l"(b), "l"(c)); return d;
}
__device__ __forceinline__ uint64_t add2(uint64_t a, uint64_t b) {
    uint64_t d; asm("add.rn.f32x2 %0, %1, %2;" : "=l"(d) : "l"(a), "l"(b)); return d;
}
__device__ __forceinline__ uint64_t mul2(uint64_t a, uint64_t b) {
    uint64_t d; asm("mul.rn.f32x2 %0, %1, %2;" : "=l"(d) : "l"(a), "l"(b)); return d;
}

// packed exp(5x) for a pair, FMA pipe only (+2 ALU int ops per lane)
__device__ __forceinline__ uint64_t fexp5_2(uint64_t x2) {
    const float KE = 7.2134752044448169f;   // 5 * log2(e)
    const float SH = 12582912.0f;           // 1.5 * 2^23
    const uint64_t KE2 = pk2(KE, KE);
    const uint64_t SH2 = pk2(SH, SH);
    const uint64_t N12 = pk2(-1.0f, -1.0f);
    uint64_t z2 = fma2(x2, KE2, SH2);
    float zl, zh; upk2(z2, zl, zh);
    int e0 = (__float_as_int(zl) - 0x4B3FFF81) << 23;   // (ei - 0x4B400000 + 127) << 23
    int e1 = (__float_as_int(zh) - 0x4B3FFF81) << 23;
    uint64_t nr2 = fma2(z2, N12, SH2);                  // SH - z = -round(t)
    uint64_t f2 = fma2(x2, KE2, nr2);                   // frac in [-0.5, 0.5]
    uint64_t p = pk2(9.6181291076284771e-3f, 9.6181291076284771e-3f);
    p = fma2(p, f2, pk2(5.5504108664821580e-2f, 5.5504108664821580e-2f));
    p = fma2(p, f2, pk2(2.4022650695910071e-1f, 2.4022650695910071e-1f));
    p = fma2(p, f2, pk2(6.9314718055994531e-1f, 6.9314718055994531e-1f));
    p = fma2(p, f2, pk2(1.0f, 1.0f));
    return mul2(p, pk2(__int_as_float(e0), __int_as_float(e1)));
}

// ---------------- scalar FMA-only exp(5x) ----------------
__device__ __forceinline__ float fexp5(float x) {
    const float KE = 7.2134752044448169f;
    const float SH = 12582912.0f;
    float z = fmaf(x, KE, SH);
    int   ei = __float_as_int(z);
    float r = z - SH;
    float f = fmaf(x, KE, -r);
    float p = 9.6181291076284771e-3f;
    p = fmaf(p, f, 5.5504108664821580e-2f);
    p = fmaf(p, f, 2.4022650695910071e-1f);
    p = fmaf(p, f, 6.9314718055994531e-1f);
    p = fmaf(p, f, 1.0f);
    return p * __int_as_float((ei - 0x4B400000 + 127) << 23);
}

// ---------------- merged prep + hi/lo conversions (one launch) ----------------
// float4 segment bounds (compile-time)
#define SEG_X   2097152
#define SEG_W1F 2162688
#define SEG_W1C 2228224
#define SEG_W2F 2232320
#define SEG_W2C 2240512
#define CONV_BLKS 8752          // SEG_W2C / 256

__global__ void prep_conv_kernel(const float* __restrict__ roi,
                                 const float* __restrict__ w1f, const float* __restrict__ w1c,
                                 const float* __restrict__ w2f, const float* __restrict__ w2c,
                                 const int* __restrict__ lraw, const float* __restrict__ ious) {
    if (blockIdx.x >= CONV_BLKS) {
        // prep path: one thread per row
        int i = (blockIdx.x - CONV_BLKS) * 256 + threadIdx.x;
        bool is64 = true;
        #pragma unroll 1
        for (int p = 0; p < 32; ++p) {
            int lo = lraw[2 * p], hi = lraw[2 * p + 1];
            bool ok = (hi == 0 && lo >= 0) || (hi == -1 && lo < 0);
            if (!ok) { is64 = false; break; }
        }
        int l = is64 ? (int)(((const long long*)lraw)[i]) : lraw[i];
        g_lbl[i] = l;
        g_fgf[i] = (l > 0) ? 1.0f : 0.0f;
        g_vld[i] = (l != -1) ? 1.0f : 0.0f;
        float u = ious[i];
        g_wgt[i] = (u > 0.5f) ? u : 0.0f;
        return;
    }
    int i = blockIdx.x * 256 + threadIdx.x;
    const float* s; __nv_bfloat16 *h, *l; int base;
    if (i < SEG_X)        { s = roi; h = g_Xh;   l = g_Xl;   base = 0; }
    else if (i < SEG_W1F) { s = w1f; h = g_W1fh; l = g_W1fl; base = SEG_X; }
    else if (i < SEG_W1C) { s = w1c; h = g_W1ch; l = g_W1cl; base = SEG_W1F; }
    else if (i < SEG_W2F) { s = w2f; h = g_W2fh; l = g_W2fl; base = SEG_W1C; }
    else                  { s = w2c; h = g_W2ch; l = g_W2cl; base = SEG_W2F; }
    int j = i - base;
    float4 v = ((const float4*)s)[j];
    __nv_bfloat162 h0, h1, l0, l1;
    h0.x = __float2bfloat16(v.x); h0.y = __float2bfloat16(v.y);
    h1.x = __float2bfloat16(v.z); h1.y = __float2bfloat16(v.w);
    l0.x = __float2bfloat16(v.x - __bfloat162float(h0.x));
    l0.y = __float2bfloat16(v.y - __bfloat162float(h0.y));
    l1.x = __float2bfloat16(v.z - __bfloat162float(h1.x));
    l1.y = __float2bfloat16(v.w - __bfloat162float(h1.y));
    ((__nv_bfloat162*)h)[j * 2] = h0; ((__nv_bfloat162*)h)[j * 2 + 1] = h1;
    ((__nv_bfloat162*)l)[j * 2] = l0; ((__nv_bfloat162*)l)[j * 2 + 1] = l1;
}

// ---------------- cp.async bf16 tile loader (BK=64, padded stride 144B) ----------------
__device__ __forceinline__ void ld_tile64(uint32_t dst, const __nv_bfloat16* __restrict__ src,
                                          int rows, int K, int tid) {
    #pragma unroll 4
    for (int i = tid; i < rows * 8; i += 256) {
        int r = i >> 3, c = i & 7;
        asm volatile("cp.async.cg.shared.global [%0], [%1], 16;"
                     :: "r"(dst + r * 144 + c * 16), "l"(src + (size_t)r * K + c * 8) : "memory");
    }
}

// ---------------- MMA GEMM (MLP): 3-chain hi/lo ----------------
template<int BN, bool RELU_SPLIT>
__global__ __launch_bounds__(256) void mma_gemm(
    const __nv_bfloat16* __restrict__ Ah0, const __nv_bfloat16* __restrict__ Al0,
    const __nv_bfloat16* __restrict__ Ah1, const __nv_bfloat16* __restrict__ Al1,
    const __nv_bfloat16* __restrict__ Wh0, const __nv_bfloat16* __restrict__ Wl0,
    const __nv_bfloat16* __restrict__ Wh1, const __nv_bfloat16* __restrict__ Wl1,
    const float* __restrict__ bias0, const float* __restrict__ bias1,
    void* __restrict__ o0a, void* __restrict__ o0b,
    void* __restrict__ o1a, void* __restrict__ o1b,
    int N, int K) {
    constexpr int SA = 144;
    constexpr int ATS = 128 * SA;
    constexpr int BTS = BN * SA;
    constexpr int STG = 2 * ATS + 2 * BTS;
    constexpr int NG = BN / 32;
    constexpr int NF = 2 * NG;

    extern __shared__ char smem[];
    uint32_t sb = smem_u32(smem);
    const int tid = threadIdx.x, wid = tid >> 5, lane = tid & 31;
    const int wm = wid & 3, wn = wid >> 2;
    const int z = blockIdx.z;
    const int bm = blockIdx.y * 128, bn = blockIdx.x * BN;

    const __nv_bfloat16* Ah = z ? Ah1 : Ah0;
    const __nv_bfloat16* Al = z ? Al1 : Al0;
    const __nv_bfloat16* Wh = z ? Wh1 : Wh0;
    const __nv_bfloat16* Wl = z ? Wl1 : Wl0;
    const float* bias = z ? bias1 : bias0;

    const int KC = K >> 6;

    ld_tile64(sb, Ah + (size_t)bm * K, 128, K, tid);
    ld_tile64(sb + ATS, Al + (size_t)bm * K, 128, K, tid);
    ld_tile64(sb + 2 * ATS, Wh + (size_t)bn * K, BN, K, tid);
    ld_tile64(sb + 2 * ATS + BTS, Wl + (size_t)bn * K, BN, K, tid);
    asm volatile("cp.async.commit_group;" ::: "memory");

    float acc[2][NF][4];
    #pragma unroll
    for (int ma = 0; ma < 2; ++ma)
        #pragma unroll
        for (int nf = 0; nf < NF; ++nf)
            #pragma unroll
            for (int e = 0; e < 4; ++e) acc[ma][nf][e] = 0.0f;

    const uint32_t a_off = (uint32_t)((wm * 32 + (lane & 15)) * SA + (lane >> 4) * 16);
    const uint32_t b_off = (uint32_t)((wn * (BN / 2) + ((lane >> 4) << 3) + (lane & 7)) * SA + ((lane >> 3) & 1) * 16);

    for (int kc = 0; kc < KC; ++kc) {
        const uint32_t cur = sb + (kc & 1) * STG;
        if (kc + 1 < KC) {
            const uint32_t nxt = sb + ((kc + 1) & 1) * STG;
            const int ko = (kc + 1) * 64;
            ld_tile64(nxt, Ah + (size_t)bm * K + ko, 128, K, tid);
            ld_tile64(nxt + ATS, Al + (size_t)bm * K + ko, 128, K, tid);
            ld_tile64(nxt + 2 * ATS, Wh + (size_t)bn * K + ko, BN, K, tid);
            ld_tile64(nxt + 2 * ATS + BTS, Wl + (size_t)bn * K + ko, BN, K, tid);
            asm volatile("cp.async.commit_group;" ::: "memory");
            asm volatile("cp.async.wait_group 1;" ::: "memory");
        } else {
            asm volatile("cp.async.wait_group 0;" ::: "memory");
        }
        __syncthreads();

        #pragma unroll
        for (int ks = 0; ks < 4; ++ks) {
            const uint32_t kb = ks * 32;
            uint32_t a_h[2][4], a_l[2][4], b_h[NG][4], b_l[NG][4];
            #pragma unroll
            for (int ma = 0; ma < 2; ++ma) {
                LDSM4(a_h[ma], cur + a_off + ma * 16 * SA + kb);
                LDSM4(a_l[ma], cur + ATS + a_off + ma * 16 * SA + kb);
            }
            #pragma unroll
            for (int g = 0; g < NG; ++g) {
                LDSM4(b_h[g], cur + 2 * ATS + b_off + g * 16 * SA + kb);
                LDSM4(b_l[g], cur + 2 * ATS + BTS + b_off + g * 16 * SA + kb);
            }
            #pragma unroll
            for (int ma = 0; ma < 2; ++ma)
                #pragma unroll
                for (int g = 0; g < NG; ++g) {
                    MMA16816(acc[ma][2 * g],     a_h[ma], b_h[g][0], b_h[g][1]);
                    MMA16816(acc[ma][2 * g + 1], a_h[ma], b_h[g][2], b_h[g][3]);
                    MMA16816(acc[ma][2 * g],     a_h[ma], b_l[g][0], b_l[g][1]);
                    MMA16816(acc[ma][2 * g + 1], a_h[ma], b_l[g][2], b_l[g][3]);
                    MMA16816(acc[ma][2 * g],     a_l[ma], b_h[g][0], b_h[g][1]);
                    MMA16816(acc[ma][2 * g + 1], a_l[ma], b_h[g][2], b_h[g][3]);
                }
        }
        __syncthreads();
    }

    #pragma unroll
    for (int ma = 0; ma < 2; ++ma)
        #pragma unroll
        for (int nf = 0; nf < NF; ++nf)
            #pragma unroll
            for (int rp = 0; rp < 2; ++rp) {
                const int r = bm + wm * 32 + ma * 16 + rp * 8 + (lane >> 2);
                const int c = bn + wn * (BN / 2) + nf * 8 + (lane & 3) * 2;
                float2 bb = *(const float2*)(bias + c);
                float v0 = acc[ma][nf][rp * 2 + 0] + bb.x;
                float v1 = acc[ma][nf][rp * 2 + 1] + bb.y;
                if (RELU_SPLIT) {
                    v0 = fmaxf(v0, 0.0f); v1 = fmaxf(v1, 0.0f);
                    __nv_bfloat16* oh = (__nv_bfloat16*)(z ? o1a : o0a);
                    __nv_bfloat16* ol = (__nv_bfloat16*)(z ? o1b : o0b);
                    __nv_bfloat162 hv, lv;
                    hv.x = __float2bfloat16(v0); hv.y = __float2bfloat16(v1);
                    lv.x = __float2bfloat16(v0 - __bfloat162float(hv.x));
                    lv.y = __float2bfloat16(v1 - __bfloat162float(hv.y));
                    *(__nv_bfloat162*)(oh + (size_t)r * N + c) = hv;
                    *(__nv_bfloat162*)(ol + (size_t)r * N + c) = lv;
                } else {
                    float* of = (float*)(z ? o1a : o0a);
                    float2 ov; ov.x = v0; ov.y = v1;
                    *(float2*)(of + (size_t)r * N + c) = ov;
                }
            }
}

// ---------------- merged row L2-normalize + hi/lo split (both heads) ----------------
template<int KD>
__device__ __forceinline__ void norm_one(float* Z, __nv_bfloat16* Oh, __nv_bfloat16* Ol,
                                         int row, int lane) {
    float ss = 0.0f;
    #pragma unroll
    for (int c = lane; c < KD; c += 32) { float v = Z[(size_t)row * KD + c]; ss += v * v; }
    #pragma unroll
    for (int o = 16; o; o >>= 1) ss += __shfl_xor_sync(0xffffffffu, ss, o);
    float inv = 1.0f / fmaxf(sqrtf(ss), 1e-8f);
    #pragma unroll
    for (int c = lane; c < KD; c += 32) {
        float v = Z[(size_t)row * KD + c] * inv;
        Z[(size_t)row * KD + c] = v;
        __nv_bfloat16 h = __float2bfloat16(v);
        Oh[(size_t)row * KD + c] = h;
        Ol[(size_t)row * KD + c] = __float2bfloat16(v - __bfloat162float(h));
    }
}
__global__ void norm_conv_all_kernel() {
    int lane = threadIdx.x & 31;
    if (blockIdx.x < NR / 8) {
        int row = blockIdx.x * 8 + (threadIdx.x >> 5);
        norm_one<FGDIM>(g_Zf, g_Zfh, g_Zfl, row, lane);
    } else {
        int row = (blockIdx.x - NR / 8) * 8 + (threadIdx.x >> 5);
        norm_one<CLDIM>(g_Zc, g_Zch, g_Zcl, row, lane);
    }
}

// ---------------- per-class z sums ----------------
__global__ void class_sum1_kernel() {     // grid (20, 16), block CLDIM
    const int c = blockIdx.x + 1;
    const int d = threadIdx.x;
    const int i0 = blockIdx.y * (NR / 16);
    float s = 0.0f;
    for (int i = i0; i < i0 + NR / 16; ++i)
        if (g_lbl[i] == c) s += g_Zc[(size_t)i * CLDIM + d];
    g_Sp[(blockIdx.x * 16 + blockIdx.y) * CLDIM + d] = s;
}
__global__ void class_sum2_kernel() {     // grid 20, block CLDIM
    float s = 0.0f;
    #pragma unroll
    for (int g = 0; g < 16; ++g) s += g_Sp[(blockIdx.x * 16 + g) * CLDIM + threadIdx.x];
    g_S[blockIdx.x * CLDIM + threadIdx.x] = s;
}

// ---------------- per-row diag exps + CLS sum_pos (warp per row) ----------------
__global__ void row_sp_kernel() {
    int row = blockIdx.x * 8 + (threadIdx.x >> 5);
    int lane = threadIdx.x & 31;
    float df = 0.0f;
    #pragma unroll
    for (int c = lane; c < FGDIM; c += 32)
        df += g_Zf[(size_t)row * FGDIM + c] * __bfloat162float(g_Zfh[(size_t)row * FGDIM + c]);
    int l = g_lbl[row];
    const float* S = g_S + (l > 0 ? (l - 1) : 0) * CLDIM;
    float dc = 0.0f, ss = 0.0f, sd = 0.0f;
    #pragma unroll
    for (int c = lane; c < CLDIM; c += 32) {
        float zv = g_Zc[(size_t)row * CLDIM + c];
        dc += zv * __bfloat162float(g_Zch[(size_t)row * CLDIM + c]);
        ss += zv * zv;
        sd += zv * S[c];
    }
    #pragma unroll
    for (int o = 16; o; o >>= 1) {
        df += __shfl_xor_sync(0xffffffffu, df, o);
        dc += __shfl_xor_sync(0xffffffffu, dc, o);
        ss += __shfl_xor_sync(0xffffffffu, ss, o);
        sd += __shfl_xor_sync(0xffffffffu, sd, o);
    }
    if (lane == 0) {
        g_eiif[row] = fexp5(df);
        g_eiic[row] = fexp5(dc);
        g_sp[row] = 5.0f * (sd - ss);
    }
}

// ---------------- cp.async tile loader for sim (full K resident) ----------------
template<int KD>
__device__ __forceinline__ void load_tile(uint32_t dst, const __nv_bfloat16* __restrict__ src, int tid) {
    constexpr int CPR = KD / 8;
    constexpr int SA = KD * 2 + 16;
    #pragma unroll
    for (int i = tid; i < 128 * CPR; i += 256) {
        int r = i / CPR, c = i % CPR;
        asm volatile("cp.async.cg.shared.global [%0], [%1], 16;"
                     :: "r"(dst + r * SA + c * 16), "l"(src + (size_t)r * KD + c * 8) : "memory");
    }
}

// ---------------- warp-MMA fused sim kernel (2-chain, packed f32x2 epilogue) ----------------
template<int KD, bool CLS, int NSPLT>
__global__ __launch_bounds__(256) void sim_mma_kernel() {
    constexpr int SA = KD * 2 + 16;
    constexpr int TSZ = 128 * SA;
    constexpr int SLAB = NR / NSPLT;
    constexpr int TCOLS = SLAB / 128;
    constexpr int KSTEPS = KD / 16;
    constexpr int A_HI = SLAB * 4;
    constexpr int A_LO = A_HI + TSZ;
    constexpr int B_OFF = A_LO + TSZ;

    extern __shared__ char smem[];
    float* slab = (float*)smem;
    uint32_t sb = smem_u32(smem);
    const int tid = threadIdx.x, wid = tid >> 5, lane = tid & 31;
    const int wm = wid & 3, wn = wid >> 2;
    const int bm = blockIdx.x * 128;
    const int c0 = blockIdx.y * SLAB;
    const __nv_bfloat16* Zh = CLS ? g_Zch : g_Zfh;
    const __nv_bfloat16* Zl = CLS ? g_Zcl : g_Zfl;
    const float* flg = CLS ? g_vld : g_fgf;

    for (int i = tid; i < SLAB; i += 256)
        slab[i] = flg[c0 + i];

    load_tile<KD>(sb + A_HI, Zh + (size_t)bm * KD, tid);
    load_tile<KD>(sb + A_LO, Zl + (size_t)bm * KD, tid);
    load_tile<KD>(sb + B_OFF, Zh + (size_t)c0 * KD, tid);
    asm volatile("cp.async.commit_group;" ::: "memory");

    uint64_t dn2[2][2] = {{0ull, 0ull}, {0ull, 0ull}};
    uint64_t x12[2][2] = {{0ull, 0ull}, {0ull, 0ull}};

    const uint32_t a_off = (uint32_t)((wm * 32 + (lane & 15)) * SA + (lane >> 4) * 16);
    const uint32_t b_off = (uint32_t)((wn * 64 + ((lane >> 4) << 3) + (lane & 7)) * SA + ((lane >> 3) & 1) * 16);

    float acc[2][8][4];
    #pragma unroll
    for (int ma = 0; ma < 2; ++ma)
        #pragma unroll
        for (int na = 0; na < 8; ++na)
            #pragma unroll
            for (int e = 0; e < 4; ++e) acc[ma][na][e] = 0.0f;

    asm volatile("cp.async.wait_group 0;" ::: "memory");
    __syncthreads();

    for (int t = 0; t < TCOLS; ++t) {
        const uint32_t bcur = sb + B_OFF + (t & 1) * TSZ;
        if (t + 1 < TCOLS) {
            load_tile<KD>(sb + B_OFF + ((t + 1) & 1) * TSZ,
                          Zh + (size_t)(c0 + (t + 1) * 128) * KD, tid);
            asm volatile("cp.async.commit_group;" ::: "memory");
        }

        #pragma unroll
        for (int ks = 0; ks < KSTEPS; ++ks) {
            uint32_t a_h[2][4], a_l[2][4], b_h[4][4];
            const uint32_t kb = ks * 32;
            #pragma unroll
            for (int ma = 0; ma < 2; ++ma) {
                LDSM4(a_h[ma], sb + A_HI + a_off + ma * 16 * SA + kb);
                LDSM4(a_l[ma], sb + A_LO + a_off + ma * 16 * SA + kb);
            }
            #pragma unroll
            for (int g = 0; g < 4; ++g)
                LDSM4(b_h[g], bcur + b_off + g * 16 * SA + kb);
            #pragma unroll
            for (int ma = 0; ma < 2; ++ma)
                #pragma unroll
                for (int g = 0; g < 4; ++g) {
                    MMA16816(acc[ma][2 * g],     a_h[ma], b_h[g][0], b_h[g][1]);
                    MMA16816(acc[ma][2 * g + 1], a_h[ma], b_h[g][2], b_h[g][3]);
                    MMA16816(acc[ma][2 * g],     a_l[ma], b_h[g][0], b_h[g][1]);
                    MMA16816(acc[ma][2 * g + 1], a_l[ma], b_h[g][2], b_h[g][3]);
                }
        }

        // packed epilogue: e = exp(5v); dn += e (*flag for CLS); x1 += e*flag (FG)
        const int tb = t * 128;
        #pragma unroll
        for (int ma = 0; ma < 2; ++ma)
            #pragma unroll
            for (int na = 0; na < 8; ++na) {
                const int cA = wn * 64 + na * 8 + (lane & 3) * 2;
                const float2 lp = *(const float2*)(slab + tb + cA);
                const uint64_t fl2 = pk2(lp.x, lp.y);
                float* c = acc[ma][na];
                uint64_t ea = fexp5_2(pk2(c[0], c[1]));   // rp = 0
                uint64_t eb = fexp5_2(pk2(c[2], c[3]));   // rp = 1
                if (CLS) {
                    dn2[ma][0] = fma2(ea, fl2, dn2[ma][0]);
                    dn2[ma][1] = fma2(eb, fl2, dn2[ma][1]);
                } else {
                    dn2[ma][0] = add2(dn2[ma][0], ea);
                    dn2[ma][1] = add2(dn2[ma][1], eb);
                    x12[ma][0] = fma2(ea, fl2, x12[ma][0]);
                    x12[ma][1] = fma2(eb, fl2, x12[ma][1]);
                }
                c[0] = 0.0f; c[1] = 0.0f; c[2] = 0.0f; c[3] = 0.0f;
            }

        if (t + 1 < TCOLS) {
            asm volatile("cp.async.wait_group 0;" ::: "memory");
        }
        __syncthreads();
    }

    // fold packed halves, then quad reduction
    float dn[2][2], x1[2][2];
    #pragma unroll
    for (int ma = 0; ma < 2; ++ma)
        #pragma unroll
        for (int rp = 0; rp < 2; ++rp) {
            float a, b;
            upk2(dn2[ma][rp], a, b); dn[ma][rp] = a + b;
            upk2(x12[ma][rp], a, b); x1[ma][rp] = a + b;
            #pragma unroll
            for (int o = 1; o <= 2; o <<= 1) {
                dn[ma][rp] += __shfl_xor_sync(0xffffffffu, dn[ma][rp], o);
                if (!CLS) x1[ma][rp] += __shfl_xor_sync(0xffffffffu, x1[ma][rp], o);
            }
        }

    float* red = (float*)smem;
    __syncthreads();
    if (wn == 1 && (lane & 3) == 0) {
        #pragma unroll
        for (int ma = 0; ma < 2; ++ma)
            #pragma unroll
            for (int rp = 0; rp < 2; ++rp) {
                int rl = wm * 32 + ma * 16 + rp * 8 + (lane >> 2);
                red[rl * 2 + 0] = dn[ma][rp];
                red[rl * 2 + 1] = x1[ma][rp];
            }
    }
    __syncthreads();
    if (wn == 0 && (lane & 3) == 0) {
        const int s = blockIdx.y;
        #pragma unroll
        for (int ma = 0; ma < 2; ++ma)
            #pragma unroll
            for (int rp = 0; rp < 2; ++rp) {
                int rl = wm * 32 + ma * 16 + rp * 8 + (lane >> 2);
                float a = dn[ma][rp] + red[rl * 2 + 0];
                int g = bm + rl;
                if (CLS) {
                    g_pcl[(size_t)s * NR + g] = a;
                } else {
                    float b = x1[ma][rp] + red[rl * 2 + 1];
                    g_pfg[((size_t)s * NR + g) * 2 + 0] = a;
                    g_pfg[((size_t)s * NR + g) * 2 + 1] = b;
                }
            }
    }
}

// ---------------- final deterministic reduction (hist computed here) ----------------
__global__ void finalize_kernel(float* __restrict__ out) {
    __shared__ int hist[22];
    __shared__ float red[256][4];
    int tid = threadIdx.x;
    if (tid < 22) hist[tid] = 0;
    __syncthreads();
    for (int i = tid; i < NR; i += 256) atomicAdd(&hist[g_lbl[i] + 1], 1);
    __syncthreads();
    int nnon = NR - hist[0];
    int nfgset = nnon - hist[1];
    float nfg = 0.0f, dfg = 0.0f, ncl = 0.0f, dcl = 0.0f;
    for (int i = tid; i < NR; i += 256) {
        int l = g_lbl[i];
        if (l > 0) {
            float w = g_wgt[i];
            float dnv = 0.0f, nm = 0.0f;
            #pragma unroll
            for (int s = 0; s < NSPL_FG; ++s) {
                dnv += g_pfg[((size_t)s * NR + i) * 2 + 0];
                nm  += g_pfg[((size_t)s * NR + i) * 2 + 1];
            }
            float ef = g_eiif[i];
            dnv -= ef; nm -= ef;
            if (nfgset - 1 > 0) {
                float li = -logf((nm + 1e-8f) / (dnv + 1e-8f));
                nfg += li * w; dfg += w;
            }
            float dc = 0.0f;
            #pragma unroll
            for (int s = 0; s < NSPL_CLS; ++s)
                dc += g_pcl[(size_t)s * NR + i];
            dc -= g_eiic[i];
            float np = (float)(hist[l + 1] - 1);
            if (np > 0.5f && (nnon - 1) > 0) {
                float li = -(g_sp[i] - np * logf(dc)) / np;
                ncl += li * w; dcl += w;
            }
        }
    }
    red[tid][0] = nfg; red[tid][1] = dfg; red[tid][2] = ncl; red[tid][3] = dcl;
    __syncthreads();
    for (int s = 128; s > 0; s >>= 1) {
        if (tid < s) {
            red[tid][0] += red[tid + s][0]; red[tid][1] += red[tid + s][1];
            red[tid][2] += red[tid + s][2]; red[tid][3] += red[tid + s][3];
        }
        __syncthreads();
    }
    if (tid == 0) {
        out[0] = red[0][0] / (red[0][1] + 1e-8f);
        out[1] = red[0][2] / (red[0][3] + 1e-12f);
    }
}

// ---------------- launch ----------------
extern "C" void kernel_launch(void* const* d_in, const int* in_sizes, int n_in,
                              void* d_out, int out_size) {
    const float* roi = (const float*)d_in[0];
    const int*   lab = (const int*)d_in[1];
    const float* iou = (const float*)d_in[2];
    const float* w1f = (const float*)d_in[3];
    const float* b1f = (const float*)d_in[4];
    const float* w2f = (const float*)d_in[5];
    const float* b2f = (const float*)d_in[6];
    const float* w1c = (const float*)d_in[7];
    const float* b1c = (const float*)d_in[8];
    const float* w2c = (const float*)d_in[9];
    const float* b2c = (const float*)d_in[10];

    __nv_bfloat16 *Xh, *Xl, *W1fh, *W1fl, *W1ch, *W1cl, *W2fh, *W2fl, *W2ch, *W2cl;
    __nv_bfloat16 *Hfh, *Hfl, *Hch, *Hcl;
    float *Zf, *Zc;
    cudaGetSymbolAddress((void**)&Xh, g_Xh);     cudaGetSymbolAddress((void**)&Xl, g_Xl);
    cudaGetSymbolAddress((void**)&W1fh, g_W1fh); cudaGetSymbolAddress((void**)&W1fl, g_W1fl);
    cudaGetSymbolAddress((void**)&W1ch, g_W1ch); cudaGetSymbolAddress((void**)&W1cl, g_W1cl);
    cudaGetSymbolAddress((void**)&W2fh, g_W2fh); cudaGetSymbolAddress((void**)&W2fl, g_W2fl);
    cudaGetSymbolAddress((void**)&W2ch, g_W2ch); cudaGetSymbolAddress((void**)&W2cl, g_W2cl);
    cudaGetSymbolAddress((void**)&Hfh, g_Hfh);   cudaGetSymbolAddress((void**)&Hfl, g_Hfl);
    cudaGetSymbolAddress((void**)&Hch, g_Hch);   cudaGetSymbolAddress((void**)&Hcl, g_Hcl);
    cudaGetSymbolAddress((void**)&Zf, g_Zf);     cudaGetSymbolAddress((void**)&Zc, g_Zc);

    constexpr int SM_G128 = 2 * (2 * 128 * 144 + 2 * 128 * 144);
    constexpr int SM_G64  = 2 * (2 * 128 * 144 + 2 * 64 * 144);
    constexpr int SMEM_FG  = (NR / NSPL_FG) * 4 + 4 * 128 * (FGDIM * 2 + 16);
    constexpr int SMEM_CLS = (NR / NSPL_CLS) * 4 + 4 * 128 * (CLDIM * 2 + 16);
    cudaFuncSetAttribute(mma_gemm<128, true>,  cudaFuncAttributeMaxDynamicSharedMemorySize, SM_G128);
    cudaFuncSetAttribute(mma_gemm<128, false>, cudaFuncAttributeMaxDynamicSharedMemorySize, SM_G128);
    cudaFuncSetAttribute(mma_gemm<64, false>,  cudaFuncAttributeMaxDynamicSharedMemorySize, SM_G64);
    cudaFuncSetAttribute(sim_mma_kernel<FGDIM, false, NSPL_FG>, cudaFuncAttributeMaxDynamicSharedMemorySize, SMEM_FG);
    cudaFuncSetAttribute(sim_mma_kernel<CLDIM, true, NSPL_CLS>, cudaFuncAttributeMaxDynamicSharedMemorySize, SMEM_CLS);

    // merged prep + all hi/lo conversions (1 launch)
    prep_conv_kernel<<<CONV_BLKS + NR / 256, 256>>>(roi, w1f, w1c, w2f, w2c, lab, iou);

    // layer 1 (both heads): H = relu(X @ W1^T + b1), bf16 hi/lo out
    mma_gemm<128, true><<<dim3(HD / 128, NR / 128, 2), 256, SM_G128>>>(
        Xh, Xl, Xh, Xl, W1fh, W1fl, W1ch, W1cl, b1f, b1c,
        Hfh, Hfl, Hch, Hcl, HD, CD);

    // layer 2: Z = H @ W2^T + b2 (fp32 out)
    mma_gemm<64, false><<<dim3(1, NR / 128, 1), 256, SM_G64>>>(
        Hfh, Hfl, Hfh, Hfl, W2fh, W2fl, W2fh, W2fl, b2f, b2f,
        Zf, nullptr, Zf, nullptr, FGDIM, HD);
    mma_gemm<128, false><<<dim3(1, NR / 128, 1), 256, SM_G128>>>(
        Hch, Hcl, Hch, Hcl, W2ch, W2cl, W2ch, W2cl, b2c, b2c,
        Zc, nullptr, Zc, nullptr, CLDIM, HD);

    // normalize + split, both heads, one launch
    norm_conv_all_kernel<<<2 * (NR / 8), 256>>>();

    class_sum1_kernel<<<dim3(20, 16), CLDIM>>>();
    class_sum2_kernel<<<20, CLDIM>>>();
    row_sp_kernel<<<NR / 8, 256>>>();

    sim_mma_kernel<FGDIM, false, NSPL_FG><<<dim3(64, NSPL_FG), 256, SMEM_FG>>>();
    sim_mma_kernel<CLDIM, true, NSPL_CLS><<<dim3(64, NSPL_CLS), 256, SMEM_CLS>>>();

    finalize_kernel<<<1, 256>>>((float*)d_out);
}

// round 7
// speedup vs baseline: 4.0164x; 1.1757x over previous
#include <cuda_runtime.h>
#include <cuda_bf16.h>
#include <math.h>
#include <stdint.h>

#define NR 8192
#define CD 1024
#define HD 256
#define FGDIM 64
#define CLDIM 128
#define NSPL_FG 4
#define NSPL_CLS 4

// ---------------- device scratch (no allocs allowed) ----------------
__device__ __nv_bfloat16 g_Xh[NR * CD];
__device__ __nv_bfloat16 g_Xl[NR * CD];
__device__ __nv_bfloat16 g_W1fh[HD * CD];
__device__ __nv_bfloat16 g_W1fl[HD * CD];
__device__ __nv_bfloat16 g_W1ch[HD * CD];
__device__ __nv_bfloat16 g_W1cl[HD * CD];
__device__ __nv_bfloat16 g_W2fh[FGDIM * HD];
__device__ __nv_bfloat16 g_W2fl[FGDIM * HD];
__device__ __nv_bfloat16 g_W2ch[CLDIM * HD];
__device__ __nv_bfloat16 g_W2cl[CLDIM * HD];
__device__ __nv_bfloat16 g_Hfh[NR * HD];
__device__ __nv_bfloat16 g_Hfl[NR * HD];
__device__ __nv_bfloat16 g_Hch[NR * HD];
__device__ __nv_bfloat16 g_Hcl[NR * HD];
__device__ float g_Zf[NR * FGDIM];
__device__ float g_Zc[NR * CLDIM];
__device__ __nv_bfloat16 g_Zfh[NR * FGDIM];
__device__ __nv_bfloat16 g_Zfl[NR * FGDIM];   // kept for layout symmetry (unused by sims now)
__device__ __nv_bfloat16 g_Zch[NR * CLDIM];
__device__ __nv_bfloat16 g_Zcl[NR * CLDIM];   // unused by sims now
__device__ float g_pfg[NSPL_FG * NR * 2];     // per split, per row: denom, numer
__device__ float g_pcl[NSPL_CLS * NR];        // per split, per row: denom
__device__ float g_Sp[20 * 16 * CLDIM];       // per-class partial sums
__device__ float g_S[20 * CLDIM];             // per-class z sums
__device__ float g_sp[NR];                    // per-row sum_pos (CLS)
__device__ float g_eiif[NR];                  // per-row self exp (FG, hi*hi)
__device__ float g_eiic[NR];                  // per-row self exp (CLS, hi*hi)
__device__ float g_ssf[NR];                   // per-row ||z||^2 (FG, unused)
__device__ float g_ssc[NR];                   // per-row ||z||^2 (CLS)
__device__ int   g_lbl[NR];
__device__ float g_fgf[NR];                   // fg flag as float
__device__ float g_vld[NR];                   // ~ignore flag as float
__device__ float g_wgt[NR];

// ---------------- helpers ----------------
__device__ __forceinline__ uint32_t smem_u32(const void* p) {
    uint32_t a;
    asm("{ .reg .u64 t; cvta.to.shared.u64 t, %1; cvt.u32.u64 %0, t; }" : "=r"(a) : "l"(p));
    return a;
}

#define LDSM4(r, addr) \
    asm volatile("ldmatrix.sync.aligned.m8n8.x4.shared.b16 {%0,%1,%2,%3}, [%4];" \
        : "=r"((r)[0]), "=r"((r)[1]), "=r"((r)[2]), "=r"((r)[3]) : "r"(addr))

#define MMA16816(d, a, b0, b1) \
    asm volatile("mma.sync.aligned.m16n8k16.row.col.f32.bf16.bf16.f32 " \
        "{%0,%1,%2,%3},{%4,%5,%6,%7},{%8,%9},{%0,%1,%2,%3};" \
        : "+f"((d)[0]), "+f"((d)[1]), "+f"((d)[2]), "+f"((d)[3]) \
        : "r"((a)[0]), "r"((a)[1]), "r"((a)[2]), "r"((a)[3]), "r"(b0), "r"(b1))

// ---------------- packed f32x2 ops (sm_100+ base ISA) ----------------
__device__ __forceinline__ uint64_t pk2(float a, float b) {
    uint64_t r; asm("mov.b64 %0, {%1, %2};" : "=l"(r) : "f"(a), "f"(b)); return r;
}
__device__ __forceinline__ void upk2(uint64_t v, float& a, float& b) {
    asm("mov.b64 {%0, %1}, %2;" : "=f"(a), "=f"(b) : "l"(v));
}
__device__ __forceinline__ uint64_t fma2(uint64_t a, uint64_t b, uint64_t c) {
    uint64_t d; asm("fma.rn.f32x2 %0, %1, %2, %3;" : "=l"(d) : "l"(a), "l"(b), "l"(c)); return d;
}
__device__ __forceinline__ uint64_t add2(uint64_t a, uint64_t b) {
    uint64_t d; asm("add.rn.f32x2 %0, %1, %2;" : "=l"(d) : "l"(a), "l"(b)); return d;
}
__device__ __forceinline__ uint64_t mul2(uint64_t a, uint64_t b) {
    uint64_t d; asm("mul.rn.f32x2 %0, %1, %2;" : "=l"(d) : "l"(a), "l"(b)); return d;
}

// packed exp(5x) for a pair
__device__ __forceinline__ uint64_t fexp5_2(uint64_t x2) {
    const float KE = 7.2134752044448169f;   // 5 * log2(e)
    const float SH = 12582912.0f;           // 1.5 * 2^23
    const uint64_t KE2 = pk2(KE, KE);
    const uint64_t SH2 = pk2(SH, SH);
    const uint64_t N12 = pk2(-1.0f, -1.0f);
    uint64_t z2 = fma2(x2, KE2, SH2);
    float zl, zh; upk2(z2, zl, zh);
    int e0 = (__float_as_int(zl) - 0x4B3FFF81) << 23;
    int e1 = (__float_as_int(zh) - 0x4B3FFF81) << 23;
    uint64_t nr2 = fma2(z2, N12, SH2);
    uint64_t f2 = fma2(x2, KE2, nr2);
    uint64_t p = pk2(9.6181291076284771e-3f, 9.6181291076284771e-3f);
    p = fma2(p, f2, pk2(5.5504108664821580e-2f, 5.5504108664821580e-2f));
    p = fma2(p, f2, pk2(2.4022650695910071e-1f, 2.4022650695910071e-1f));
    p = fma2(p, f2, pk2(6.9314718055994531e-1f, 6.9314718055994531e-1f));
    p = fma2(p, f2, pk2(1.0f, 1.0f));
    return mul2(p, pk2(__int_as_float(e0), __int_as_float(e1)));
}

// scalar exp(5x)
__device__ __forceinline__ float fexp5(float x) {
    const float KE = 7.2134752044448169f;
    const float SH = 12582912.0f;
    float z = fmaf(x, KE, SH);
    int   ei = __float_as_int(z);
    float r = z - SH;
    float f = fmaf(x, KE, -r);
    float p = 9.6181291076284771e-3f;
    p = fmaf(p, f, 5.5504108664821580e-2f);
    p = fmaf(p, f, 2.4022650695910071e-1f);
    p = fmaf(p, f, 6.9314718055994531e-1f);
    p = fmaf(p, f, 1.0f);
    return p * __int_as_float((ei - 0x4B400000 + 127) << 23);
}

// ---------------- merged prep + hi/lo conversions (one launch) ----------------
#define SEG_X   2097152
#define SEG_W1F 2162688
#define SEG_W1C 2228224
#define SEG_W2F 2232320
#define SEG_W2C 2240512
#define CONV_BLKS 8752

__global__ void prep_conv_kernel(const float* __restrict__ roi,
                                 const float* __restrict__ w1f, const float* __restrict__ w1c,
                                 const float* __restrict__ w2f, const float* __restrict__ w2c,
                                 const int* __restrict__ lraw, const float* __restrict__ ious) {
    if (blockIdx.x >= CONV_BLKS) {
        int i = (blockIdx.x - CONV_BLKS) * 256 + threadIdx.x;
        bool is64 = true;
        #pragma unroll 1
        for (int p = 0; p < 32; ++p) {
            int lo = lraw[2 * p], hi = lraw[2 * p + 1];
            bool ok = (hi == 0 && lo >= 0) || (hi == -1 && lo < 0);
            if (!ok) { is64 = false; break; }
        }
        int l = is64 ? (int)(((const long long*)lraw)[i]) : lraw[i];
        g_lbl[i] = l;
        g_fgf[i] = (l > 0) ? 1.0f : 0.0f;
        g_vld[i] = (l != -1) ? 1.0f : 0.0f;
        float u = ious[i];
        g_wgt[i] = (u > 0.5f) ? u : 0.0f;
        return;
    }
    int i = blockIdx.x * 256 + threadIdx.x;
    const float* s; __nv_bfloat16 *h, *l; int base;
    if (i < SEG_X)        { s = roi; h = g_Xh;   l = g_Xl;   base = 0; }
    else if (i < SEG_W1F) { s = w1f; h = g_W1fh; l = g_W1fl; base = SEG_X; }
    else if (i < SEG_W1C) { s = w1c; h = g_W1ch; l = g_W1cl; base = SEG_W1F; }
    else if (i < SEG_W2F) { s = w2f; h = g_W2fh; l = g_W2fl; base = SEG_W1C; }
    else                  { s = w2c; h = g_W2ch; l = g_W2cl; base = SEG_W2F; }
    int j = i - base;
    float4 v = ((const float4*)s)[j];
    __nv_bfloat162 h0, h1, l0, l1;
    h0.x = __float2bfloat16(v.x); h0.y = __float2bfloat16(v.y);
    h1.x = __float2bfloat16(v.z); h1.y = __float2bfloat16(v.w);
    l0.x = __float2bfloat16(v.x - __bfloat162float(h0.x));
    l0.y = __float2bfloat16(v.y - __bfloat162float(h0.y));
    l1.x = __float2bfloat16(v.z - __bfloat162float(h1.x));
    l1.y = __float2bfloat16(v.w - __bfloat162float(h1.y));
    ((__nv_bfloat162*)h)[j * 2] = h0; ((__nv_bfloat162*)h)[j * 2 + 1] = h1;
    ((__nv_bfloat162*)l)[j * 2] = l0; ((__nv_bfloat162*)l)[j * 2 + 1] = l1;
}

// ---------------- cp.async bf16 tile loader (BK=64, padded stride 144B) ----------------
__device__ __forceinline__ void ld_tile64(uint32_t dst, const __nv_bfloat16* __restrict__ src,
                                          int rows, int K, int tid) {
    #pragma unroll 4
    for (int i = tid; i < rows * 8; i += 256) {
        int r = i >> 3, c = i & 7;
        asm volatile("cp.async.cg.shared.global [%0], [%1], 16;"
                     :: "r"(dst + r * 144 + c * 16), "l"(src + (size_t)r * K + c * 8) : "memory");
    }
}

// ---------------- layer-1 MMA GEMM (3-chain, relu + hi/lo split out) ----------------
__global__ __launch_bounds__(256) void mma_gemm1(
    const __nv_bfloat16* __restrict__ Ah, const __nv_bfloat16* __restrict__ Al,
    const __nv_bfloat16* __restrict__ Wh0, const __nv_bfloat16* __restrict__ Wl0,
    const __nv_bfloat16* __restrict__ Wh1, const __nv_bfloat16* __restrict__ Wl1,
    const float* __restrict__ bias0, const float* __restrict__ bias1,
    __nv_bfloat16* __restrict__ o0h, __nv_bfloat16* __restrict__ o0l,
    __nv_bfloat16* __restrict__ o1h, __nv_bfloat16* __restrict__ o1l) {
    constexpr int BN = 128, SA = 144;
    constexpr int ATS = 128 * SA;
    constexpr int BTS = BN * SA;
    constexpr int STG = 2 * ATS + 2 * BTS;
    constexpr int NG = BN / 32, NF = 2 * NG;
    constexpr int N = HD, K = CD;

    extern __shared__ char smem[];
    uint32_t sb = smem_u32(smem);
    const int tid = threadIdx.x, wid = tid >> 5, lane = tid & 31;
    const int wm = wid & 3, wn = wid >> 2;
    const int z = blockIdx.z;
    const int bm = blockIdx.y * 128, bn = blockIdx.x * BN;

    const __nv_bfloat16* Wh = z ? Wh1 : Wh0;
    const __nv_bfloat16* Wl = z ? Wl1 : Wl0;
    const float* bias = z ? bias1 : bias0;
    __nv_bfloat16* oh = z ? o1h : o0h;
    __nv_bfloat16* ol = z ? o1l : o0l;

    const int KC = K >> 6;

    ld_tile64(sb, Ah + (size_t)bm * K, 128, K, tid);
    ld_tile64(sb + ATS, Al + (size_t)bm * K, 128, K, tid);
    ld_tile64(sb + 2 * ATS, Wh + (size_t)bn * K, BN, K, tid);
    ld_tile64(sb + 2 * ATS + BTS, Wl + (size_t)bn * K, BN, K, tid);
    asm volatile("cp.async.commit_group;" ::: "memory");

    float acc[2][NF][4];
    #pragma unroll
    for (int ma = 0; ma < 2; ++ma)
        #pragma unroll
        for (int nf = 0; nf < NF; ++nf)
            #pragma unroll
            for (int e = 0; e < 4; ++e) acc[ma][nf][e] = 0.0f;

    const uint32_t a_off = (uint32_t)((wm * 32 + (lane & 15)) * SA + (lane >> 4) * 16);
    const uint32_t b_off = (uint32_t)((wn * (BN / 2) + ((lane >> 4) << 3) + (lane & 7)) * SA + ((lane >> 3) & 1) * 16);

    for (int kc = 0; kc < KC; ++kc) {
        const uint32_t cur = sb + (kc & 1) * STG;
        if (kc + 1 < KC) {
            const uint32_t nxt = sb + ((kc + 1) & 1) * STG;
            const int ko = (kc + 1) * 64;
            ld_tile64(nxt, Ah + (size_t)bm * K + ko, 128, K, tid);
            ld_tile64(nxt + ATS, Al + (size_t)bm * K + ko, 128, K, tid);
            ld_tile64(nxt + 2 * ATS, Wh + (size_t)bn * K + ko, BN, K, tid);
            ld_tile64(nxt + 2 * ATS + BTS, Wl + (size_t)bn * K + ko, BN, K, tid);
            asm volatile("cp.async.commit_group;" ::: "memory");
            asm volatile("cp.async.wait_group 1;" ::: "memory");
        } else {
            asm volatile("cp.async.wait_group 0;" ::: "memory");
        }
        __syncthreads();

        #pragma unroll
        for (int ks = 0; ks < 4; ++ks) {
            const uint32_t kb = ks * 32;
            uint32_t a_h[2][4], a_l[2][4], b_h[NG][4], b_l[NG][4];
            #pragma unroll
            for (int ma = 0; ma < 2; ++ma) {
                LDSM4(a_h[ma], cur + a_off + ma * 16 * SA + kb);
                LDSM4(a_l[ma], cur + ATS + a_off + ma * 16 * SA + kb);
            }
            #pragma unroll
            for (int g = 0; g < NG; ++g) {
                LDSM4(b_h[g], cur + 2 * ATS + b_off + g * 16 * SA + kb);
                LDSM4(b_l[g], cur + 2 * ATS + BTS + b_off + g * 16 * SA + kb);
            }
            #pragma unroll
            for (int ma = 0; ma < 2; ++ma)
                #pragma unroll
                for (int g = 0; g < NG; ++g) {
                    MMA16816(acc[ma][2 * g],     a_h[ma], b_h[g][0], b_h[g][1]);
                    MMA16816(acc[ma][2 * g + 1], a_h[ma], b_h[g][2], b_h[g][3]);
                    MMA16816(acc[ma][2 * g],     a_h[ma], b_l[g][0], b_l[g][1]);
                    MMA16816(acc[ma][2 * g + 1], a_h[ma], b_l[g][2], b_l[g][3]);
                    MMA16816(acc[ma][2 * g],     a_l[ma], b_h[g][0], b_h[g][1]);
                    MMA16816(acc[ma][2 * g + 1], a_l[ma], b_h[g][2], b_h[g][3]);
                }
        }
        __syncthreads();
    }

    #pragma unroll
    for (int ma = 0; ma < 2; ++ma)
        #pragma unroll
        for (int nf = 0; nf < NF; ++nf)
            #pragma unroll
            for (int rp = 0; rp < 2; ++rp) {
                const int r = bm + wm * 32 + ma * 16 + rp * 8 + (lane >> 2);
                const int c = bn + wn * (BN / 2) + nf * 8 + (lane & 3) * 2;
                float2 bb = *(const float2*)(bias + c);
                float v0 = fmaxf(acc[ma][nf][rp * 2 + 0] + bb.x, 0.0f);
                float v1 = fmaxf(acc[ma][nf][rp * 2 + 1] + bb.y, 0.0f);
                __nv_bfloat162 hv, lv;
                hv.x = __float2bfloat16(v0); hv.y = __float2bfloat16(v1);
                lv.x = __float2bfloat16(v0 - __bfloat162float(hv.x));
                lv.y = __float2bfloat16(v1 - __bfloat162float(hv.y));
                *(__nv_bfloat162*)(oh + (size_t)r * N + c) = hv;
                *(__nv_bfloat162*)(ol + (size_t)r * N + c) = lv;
            }
}

// ---------------- layer-2 MMA GEMM, fused normalize + split + eii/ss ----------------
// N == BN (full row in CTA). 3-chain hi/lo. Writes Z (fp32 normalized), Zh, Zl,
// eii = exp5(sum h^2), ss = ||z||^2 (post-norm).
template<int BN>
__global__ __launch_bounds__(256) void mma_gemm2(
    const __nv_bfloat16* __restrict__ Ah, const __nv_bfloat16* __restrict__ Al,
    const __nv_bfloat16* __restrict__ Wh, const __nv_bfloat16* __restrict__ Wl,
    const float* __restrict__ bias,
    float* __restrict__ Zout, __nv_bfloat16* __restrict__ Oh, __nv_bfloat16* __restrict__ Ol,
    float* __restrict__ eii, float* __restrict__ ssout) {
    constexpr int SA = 144;
    constexpr int ATS = 128 * SA;
    constexpr int BTS = BN * SA;
    constexpr int STG = 2 * ATS + 2 * BTS;
    constexpr int NG = BN / 32, NF = 2 * NG;
    constexpr int K = HD;
    constexpr int ZS = BN + 4;

    extern __shared__ char smem[];
    uint32_t sb = smem_u32(smem);
    float* zbuf = (float*)smem;
    const int tid = threadIdx.x, wid = tid >> 5, lane = tid & 31;
    const int wm = wid & 3, wn = wid >> 2;
    const int bm = blockIdx.x * 128;

    const int KC = K >> 6;

    ld_tile64(sb, Ah + (size_t)bm * K, 128, K, tid);
    ld_tile64(sb + ATS, Al + (size_t)bm * K, 128, K, tid);
    ld_tile64(sb + 2 * ATS, Wh, BN, K, tid);
    ld_tile64(sb + 2 * ATS + BTS, Wl, BN, K, tid);
    asm volatile("cp.async.commit_group;" ::: "memory");

    float acc[2][NF][4];
    #pragma unroll
    for (int ma = 0; ma < 2; ++ma)
        #pragma unroll
        for (int nf = 0; nf < NF; ++nf)
            #pragma unroll
            for (int e = 0; e < 4; ++e) acc[ma][nf][e] = 0.0f;

    const uint32_t a_off = (uint32_t)((wm * 32 + (lane & 15)) * SA + (lane >> 4) * 16);
    const uint32_t b_off = (uint32_t)((wn * (BN / 2) + ((lane >> 4) << 3) + (lane & 7)) * SA + ((lane >> 3) & 1) * 16);

    for (int kc = 0; kc < KC; ++kc) {
        const uint32_t cur = sb + (kc & 1) * STG;
        if (kc + 1 < KC) {
            const uint32_t nxt = sb + ((kc + 1) & 1) * STG;
            const int ko = (kc + 1) * 64;
            ld_tile64(nxt, Ah + (size_t)bm * K + ko, 128, K, tid);
            ld_tile64(nxt + ATS, Al + (size_t)bm * K + ko, 128, K, tid);
            ld_tile64(nxt + 2 * ATS, Wh + ko, BN, K, tid);
            ld_tile64(nxt + 2 * ATS + BTS, Wl + ko, BN, K, tid);
            asm volatile("cp.async.commit_group;" ::: "memory");
            asm volatile("cp.async.wait_group 1;" ::: "memory");
        } else {
            asm volatile("cp.async.wait_group 0;" ::: "memory");
        }
        __syncthreads();

        #pragma unroll
        for (int ks = 0; ks < 4; ++ks) {
            const uint32_t kb = ks * 32;
            uint32_t a_h[2][4], a_l[2][4], b_h[NG][4], b_l[NG][4];
            #pragma unroll
            for (int ma = 0; ma < 2; ++ma) {
                LDSM4(a_h[ma], cur + a_off + ma * 16 * SA + kb);
                LDSM4(a_l[ma], cur + ATS + a_off + ma * 16 * SA + kb);
            }
            #pragma unroll
            for (int g = 0; g < NG; ++g) {
                LDSM4(b_h[g], cur + 2 * ATS + b_off + g * 16 * SA + kb);
                LDSM4(b_l[g], cur + 2 * ATS + BTS + b_off + g * 16 * SA + kb);
            }
            #pragma unroll
            for (int ma = 0; ma < 2; ++ma)
                #pragma unroll
                for (int g = 0; g < NG; ++g) {
                    MMA16816(acc[ma][2 * g],     a_h[ma], b_h[g][0], b_h[g][1]);
                    MMA16816(acc[ma][2 * g + 1], a_h[ma], b_h[g][2], b_h[g][3]);
                    MMA16816(acc[ma][2 * g],     a_h[ma], b_l[g][0], b_l[g][1]);
                    MMA16816(acc[ma][2 * g + 1], a_h[ma], b_l[g][2], b_l[g][3]);
                    MMA16816(acc[ma][2 * g],     a_l[ma], b_h[g][0], b_h[g][1]);
                    MMA16816(acc[ma][2 * g + 1], a_l[ma], b_h[g][2], b_h[g][3]);
                }
        }
        __syncthreads();
    }

    // stash z = acc + bias into smem (fp32)
    #pragma unroll
    for (int ma = 0; ma < 2; ++ma)
        #pragma unroll
        for (int nf = 0; nf < NF; ++nf)
            #pragma unroll
            for (int rp = 0; rp < 2; ++rp) {
                const int r = wm * 32 + ma * 16 + rp * 8 + (lane >> 2);
                const int c = wn * (BN / 2) + nf * 8 + (lane & 3) * 2;
                float2 bb = *(const float2*)(bias + c);
                zbuf[r * ZS + c] = acc[ma][nf][rp * 2 + 0] + bb.x;
                zbuf[r * ZS + c + 1] = acc[ma][nf][rp * 2 + 1] + bb.y;
            }
    __syncthreads();

    // per-row normalize + split + eii/ss (each warp: 16 rows)
    constexpr int CE = BN / 32;
    for (int rr = 0; rr < 16; ++rr) {
        const int r = wid * 16 + rr;
        const int grow = bm + r;
        float v[CE];
        float ss = 0.0f;
        #pragma unroll
        for (int q = 0; q < CE; ++q) { v[q] = zbuf[r * ZS + lane + q * 32]; ss += v[q] * v[q]; }
        #pragma unroll
        for (int o = 16; o; o >>= 1) ss += __shfl_xor_sync(0xffffffffu, ss, o);
        const float inv = 1.0f / fmaxf(sqrtf(ss), 1e-8f);
        float hh = 0.0f;
        #pragma unroll
        for (int q = 0; q < CE; ++q) {
            float zv = v[q] * inv;
            Zout[(size_t)grow * BN + lane + q * 32] = zv;
            __nv_bfloat16 h = __float2bfloat16(zv);
            Oh[(size_t)grow * BN + lane + q * 32] = h;
            Ol[(size_t)grow * BN + lane + q * 32] = __float2bfloat16(zv - __bfloat162float(h));
            float hf = __bfloat162float(h);
            hh = fmaf(hf, hf, hh);
        }
        #pragma unroll
        for (int o = 16; o; o >>= 1) hh += __shfl_xor_sync(0xffffffffu, hh, o);
        if (lane == 0) {
            eii[grow] = fexp5(hh);
            ssout[grow] = ss * inv * inv;
        }
    }
}

// ---------------- per-class z sums ----------------
__global__ void class_sum1_kernel() {     // grid (20, 16), block CLDIM
    const int c = blockIdx.x + 1;
    const int d = threadIdx.x;
    const int i0 = blockIdx.y * (NR / 16);
    float s = 0.0f;
    for (int i = i0; i < i0 + NR / 16; ++i)
        if (g_lbl[i] == c) s += g_Zc[(size_t)i * CLDIM + d];
    g_Sp[(blockIdx.x * 16 + blockIdx.y) * CLDIM + d] = s;
}
__global__ void class_sum2_kernel() {     // grid 20, block CLDIM
    float s = 0.0f;
    #pragma unroll
    for (int g = 0; g < 16; ++g) s += g_Sp[(blockIdx.x * 16 + g) * CLDIM + threadIdx.x];
    g_S[blockIdx.x * CLDIM + threadIdx.x] = s;
}

// ---------------- per-row sum_pos for CLS (slim, warp per row) ----------------
__global__ void row_sp_kernel() {
    int row = blockIdx.x * 8 + (threadIdx.x >> 5);
    int lane = threadIdx.x & 31;
    int l = g_lbl[row];
    const float* S = g_S + (l > 0 ? (l - 1) : 0) * CLDIM;
    float sd = 0.0f;
    #pragma unroll
    for (int c = lane; c < CLDIM; c += 32)
        sd += g_Zc[(size_t)row * CLDIM + c] * S[c];
    #pragma unroll
    for (int o = 16; o; o >>= 1) sd += __shfl_xor_sync(0xffffffffu, sd, o);
    if (lane == 0) g_sp[row] = 5.0f * (sd - g_ssc[row]);
}

// ---------------- cp.async tile loader for sim (full K resident) ----------------
template<int KD>
__device__ __forceinline__ void load_tile(uint32_t dst, const __nv_bfloat16* __restrict__ src, int tid) {
    constexpr int CPR = KD / 8;
    constexpr int SA = KD * 2 + 16;
    #pragma unroll
    for (int i = tid; i < 128 * CPR; i += 256) {
        int r = i / CPR, c = i % CPR;
        asm volatile("cp.async.cg.shared.global [%0], [%1], 16;"
                     :: "r"(dst + r * SA + c * 16), "l"(src + (size_t)r * KD + c * 8) : "memory");
    }
}

// ---------------- warp-MMA fused sim kernel (1-chain hi*hi, packed epilogue, occ 2) ----------------
template<int KD, bool CLS, int NSPLT>
__global__ __launch_bounds__(256, 2) void sim_mma_kernel() {
    constexpr int SA = KD * 2 + 16;
    constexpr int TSZ = 128 * SA;
    constexpr int SLAB = NR / NSPLT;
    constexpr int TCOLS = SLAB / 128;
    constexpr int KSTEPS = KD / 16;
    constexpr int B_OFF = TSZ;                 // A at 0, B double buffer after

    extern __shared__ char smem[];
    uint32_t sb = smem_u32(smem);
    const int tid = threadIdx.x, wid = tid >> 5, lane = tid & 31;
    const int wm = wid & 3, wn = wid >> 2;
    const int bm = blockIdx.x * 128;
    const int c0 = blockIdx.y * SLAB;
    const __nv_bfloat16* Zh = CLS ? g_Zch : g_Zfh;
    const float* flg = CLS ? g_vld : g_fgf;

    load_tile<KD>(sb, Zh + (size_t)bm * KD, tid);
    load_tile<KD>(sb + B_OFF, Zh + (size_t)c0 * KD, tid);
    asm volatile("cp.async.commit_group;" ::: "memory");

    uint64_t dn2[2][2] = {{0ull, 0ull}, {0ull, 0ull}};
    uint64_t x12[2][2] = {{0ull, 0ull}, {0ull, 0ull}};

    const uint32_t a_off = (uint32_t)((wm * 32 + (lane & 15)) * SA + (lane >> 4) * 16);
    const uint32_t b_off = (uint32_t)((wn * 64 + ((lane >> 4) << 3) + (lane & 7)) * SA + ((lane >> 3) & 1) * 16);

    float acc[2][8][4];
    #pragma unroll
    for (int ma = 0; ma < 2; ++ma)
        #pragma unroll
        for (int na = 0; na < 8; ++na)
            #pragma unroll
            for (int e = 0; e < 4; ++e) acc[ma][na][e] = 0.0f;

    asm volatile("cp.async.wait_group 0;" ::: "memory");
    __syncthreads();

    for (int t = 0; t < TCOLS; ++t) {
        const uint32_t bcur = sb + B_OFF + (t & 1) * TSZ;
        if (t + 1 < TCOLS) {
            load_tile<KD>(sb + B_OFF + ((t + 1) & 1) * TSZ,
                          Zh + (size_t)(c0 + (t + 1) * 128) * KD, tid);
            asm volatile("cp.async.commit_group;" ::: "memory");
        }

        #pragma unroll
        for (int ks = 0; ks < KSTEPS; ++ks) {
            uint32_t a_h[2][4], b_h[4][4];
            const uint32_t kb = ks * 32;
            #pragma unroll
            for (int ma = 0; ma < 2; ++ma)
                LDSM4(a_h[ma], sb + a_off + ma * 16 * SA + kb);
            #pragma unroll
            for (int g = 0; g < 4; ++g)
                LDSM4(b_h[g], bcur + b_off + g * 16 * SA + kb);
            #pragma unroll
            for (int ma = 0; ma < 2; ++ma)
                #pragma unroll
                for (int g = 0; g < 4; ++g) {
                    MMA16816(acc[ma][2 * g],     a_h[ma], b_h[g][0], b_h[g][1]);
                    MMA16816(acc[ma][2 * g + 1], a_h[ma], b_h[g][2], b_h[g][3]);
                }
        }

        // packed epilogue, flags straight from global (L1/L2 resident)
        const int tb = c0 + t * 128;
        #pragma unroll
        for (int ma = 0; ma < 2; ++ma)
            #pragma unroll
            for (int na = 0; na < 8; ++na) {
                const int cA = wn * 64 + na * 8 + (lane & 3) * 2;
                const float2 lp = *(const float2*)(flg + tb + cA);
                const uint64_t fl2 = pk2(lp.x, lp.y);
                float* c = acc[ma][na];
                uint64_t ea = fexp5_2(pk2(c[0], c[1]));
                uint64_t eb = fexp5_2(pk2(c[2], c[3]));
                if (CLS) {
                    dn2[ma][0] = fma2(ea, fl2, dn2[ma][0]);
                    dn2[ma][1] = fma2(eb, fl2, dn2[ma][1]);
                } else {
                    dn2[ma][0] = add2(dn2[ma][0], ea);
                    dn2[ma][1] = add2(dn2[ma][1], eb);
                    x12[ma][0] = fma2(ea, fl2, x12[ma][0]);
                    x12[ma][1] = fma2(eb, fl2, x12[ma][1]);
                }
                c[0] = 0.0f; c[1] = 0.0f; c[2] = 0.0f; c[3] = 0.0f;
            }

        if (t + 1 < TCOLS) {
            asm volatile("cp.async.wait_group 0;" ::: "memory");
        }
        __syncthreads();
    }

    float dn[2][2], x1[2][2];
    #pragma unroll
    for (int ma = 0; ma < 2; ++ma)
        #pragma unroll
        for (int rp = 0; rp < 2; ++rp) {
            float a, b;
            upk2(dn2[ma][rp], a, b); dn[ma][rp] = a + b;
            upk2(x12[ma][rp], a, b); x1[ma][rp] = a + b;
            #pragma unroll
            for (int o = 1; o <= 2; o <<= 1) {
                dn[ma][rp] += __shfl_xor_sync(0xffffffffu, dn[ma][rp], o);
                if (!CLS) x1[ma][rp] += __shfl_xor_sync(0xffffffffu, x1[ma][rp], o);
            }
        }

    float* red = (float*)smem;
    __syncthreads();
    if (wn == 1 && (lane & 3) == 0) {
        #pragma unroll
        for (int ma = 0; ma < 2; ++ma)
            #pragma unroll
            for (int rp = 0; rp < 2; ++rp) {
                int rl = wm * 32 + ma * 16 + rp * 8 + (lane >> 2);
                red[rl * 2 + 0] = dn[ma][rp];
                red[rl * 2 + 1] = x1[ma][rp];
            }
    }
    __syncthreads();
    if (wn == 0 && (lane & 3) == 0) {
        const int s = blockIdx.y;
        #pragma unroll
        for (int ma = 0; ma < 2; ++ma)
            #pragma unroll
            for (int rp = 0; rp < 2; ++rp) {
                int rl = wm * 32 + ma * 16 + rp * 8 + (lane >> 2);
                float a = dn[ma][rp] + red[rl * 2 + 0];
                int g = bm + rl;
                if (CLS) {
                    g_pcl[(size_t)s * NR + g] = a;
                } else {
                    float b = x1[ma][rp] + red[rl * 2 + 1];
                    g_pfg[((size_t)s * NR + g) * 2 + 0] = a;
                    g_pfg[((size_t)s * NR + g) * 2 + 1] = b;
                }
            }
    }
}

// ---------------- final deterministic reduction ----------------
__global__ void finalize_kernel(float* __restrict__ out) {
    __shared__ int hist[22];
    __shared__ float red[256][4];
    int tid = threadIdx.x;
    if (tid < 22) hist[tid] = 0;
    __syncthreads();
    for (int i = tid; i < NR; i += 256) atomicAdd(&hist[g_lbl[i] + 1], 1);
    __syncthreads();
    int nnon = NR - hist[0];
    int nfgset = nnon - hist[1];
    float nfg = 0.0f, dfg = 0.0f, ncl = 0.0f, dcl = 0.0f;
    for (int i = tid; i < NR; i += 256) {
        int l = g_lbl[i];
        if (l > 0) {
            float w = g_wgt[i];
            float dnv = 0.0f, nm = 0.0f;
            #pragma unroll
            for (int s = 0; s < NSPL_FG; ++s) {
                dnv += g_pfg[((size_t)s * NR + i) * 2 + 0];
                nm  += g_pfg[((size_t)s * NR + i) * 2 + 1];
            }
            float ef = g_eiif[i];
            dnv -= ef; nm -= ef;
            if (nfgset - 1 > 0) {
                float li = -logf((nm + 1e-8f) / (dnv + 1e-8f));
                nfg += li * w; dfg += w;
            }
            float dc = 0.0f;
            #pragma unroll
            for (int s = 0; s < NSPL_CLS; ++s)
                dc += g_pcl[(size_t)s * NR + i];
            dc -= g_eiic[i];
            float np = (float)(hist[l + 1] - 1);
            if (np > 0.5f && (nnon - 1) > 0) {
                float li = -(g_sp[i] - np * logf(dc)) / np;
                ncl += li * w; dcl += w;
            }
        }
    }
    red[tid][0] = nfg; red[tid][1] = dfg; red[tid][2] = ncl; red[tid][3] = dcl;
    __syncthreads();
    for (int s = 128; s > 0; s >>= 1) {
        if (tid < s) {
            red[tid][0] += red[tid + s][0]; red[tid][1] += red[tid + s][1];
            red[tid][2] += red[tid + s][2]; red[tid][3] += red[tid + s][3];
        }
        __syncthreads();
    }
    if (tid == 0) {
        out[0] = red[0][0] / (red[0][1] + 1e-8f);
        out[1] = red[0][2] / (red[0][3] + 1e-12f);
    }
}

// ---------------- launch ----------------
extern "C" void kernel_launch(void* const* d_in, const int* in_sizes, int n_in,
                              void* d_out, int out_size) {
    const float* roi = (const float*)d_in[0];
    const int*   lab = (const int*)d_in[1];
    const float* iou = (const float*)d_in[2];
    const float* w1f = (const float*)d_in[3];
    const float* b1f = (const float*)d_in[4];
    const float* w2f = (const float*)d_in[5];
    const float* b2f = (const float*)d_in[6];
    const float* w1c = (const float*)d_in[7];
    const float* b1c = (const float*)d_in[8];
    const float* w2c = (const float*)d_in[9];
    const float* b2c = (const float*)d_in[10];

    __nv_bfloat16 *Xh, *Xl, *W1fh, *W1fl, *W1ch, *W1cl, *W2fh, *W2fl, *W2ch, *W2cl;
    __nv_bfloat16 *Hfh, *Hfl, *Hch, *Hcl, *Zfh, *Zfl, *Zch, *Zcl;
    float *Zf, *Zc, *eiif, *eiic, *ssf, *ssc;
    cudaGetSymbolAddress((void**)&Xh, g_Xh);     cudaGetSymbolAddress((void**)&Xl, g_Xl);
    cudaGetSymbolAddress((void**)&W1fh, g_W1fh); cudaGetSymbolAddress((void**)&W1fl, g_W1fl);
    cudaGetSymbolAddress((void**)&W1ch, g_W1ch); cudaGetSymbolAddress((void**)&W1cl, g_W1cl);
    cudaGetSymbolAddress((void**)&W2fh, g_W2fh); cudaGetSymbolAddress((void**)&W2fl, g_W2fl);
    cudaGetSymbolAddress((void**)&W2ch, g_W2ch); cudaGetSymbolAddress((void**)&W2cl, g_W2cl);
    cudaGetSymbolAddress((void**)&Hfh, g_Hfh);   cudaGetSymbolAddress((void**)&Hfl, g_Hfl);
    cudaGetSymbolAddress((void**)&Hch, g_Hch);   cudaGetSymbolAddress((void**)&Hcl, g_Hcl);
    cudaGetSymbolAddress((void**)&Zf, g_Zf);     cudaGetSymbolAddress((void**)&Zc, g_Zc);
    cudaGetSymbolAddress((void**)&Zfh, g_Zfh);   cudaGetSymbolAddress((void**)&Zfl, g_Zfl);
    cudaGetSymbolAddress((void**)&Zch, g_Zch);   cudaGetSymbolAddress((void**)&Zcl, g_Zcl);
    cudaGetSymbolAddress((void**)&eiif, g_eiif); cudaGetSymbolAddress((void**)&eiic, g_eiic);
    cudaGetSymbolAddress((void**)&ssf, g_ssf);   cudaGetSymbolAddress((void**)&ssc, g_ssc);

    constexpr int SM_G128 = 2 * (2 * 128 * 144 + 2 * 128 * 144);   // 147456
    constexpr int SM_G64  = 2 * (2 * 128 * 144 + 2 * 64 * 144);    // 110592
    constexpr int SMEM_FG  = 3 * 128 * (FGDIM * 2 + 16);           // 55296
    constexpr int SMEM_CLS = 3 * 128 * (CLDIM * 2 + 16);           // 104448
    cudaFuncSetAttribute(mma_gemm1,      cudaFuncAttributeMaxDynamicSharedMemorySize, SM_G128);
    cudaFuncSetAttribute(mma_gemm2<64>,  cudaFuncAttributeMaxDynamicSharedMemorySize, SM_G64);
    cudaFuncSetAttribute(mma_gemm2<128>, cudaFuncAttributeMaxDynamicSharedMemorySize, SM_G128);
    cudaFuncSetAttribute(sim_mma_kernel<FGDIM, false, NSPL_FG>, cudaFuncAttributeMaxDynamicSharedMemorySize, SMEM_FG);
    cudaFuncSetAttribute(sim_mma_kernel<CLDIM, true, NSPL_CLS>, cudaFuncAttributeMaxDynamicSharedMemorySize, SMEM_CLS);

    // merged prep + all hi/lo conversions
    prep_conv_kernel<<<CONV_BLKS + NR / 256, 256>>>(roi, w1f, w1c, w2f, w2c, lab, iou);

    // layer 1 (both heads): H = relu(X @ W1^T + b1), bf16 hi/lo out
    mma_gemm1<<<dim3(HD / 128, NR / 128, 2), 256, SM_G128>>>(
        Xh, Xl, W1fh, W1fl, W1ch, W1cl, b1f, b1c, Hfh, Hfl, Hch, Hcl);

    // layer 2 + fused normalize/split/eii/ss
    mma_gemm2<64><<<NR / 128, 256, SM_G64>>>(
        Hfh, Hfl, W2fh, W2fl, b2f, Zf, Zfh, Zfl, eiif, ssf);
    mma_gemm2<128><<<NR / 128, 256, SM_G128>>>(
        Hch, Hcl, W2ch, W2cl, b2c, Zc, Zch, Zcl, eiic, ssc);

    // CLS factorized positives
    class_sum1_kernel<<<dim3(20, 16), CLDIM>>>();
    class_sum2_kernel<<<20, CLDIM>>>();
    row_sp_kernel<<<NR / 8, 256>>>();

    // fused tensor-core sims
    sim_mma_kernel<FGDIM, false, NSPL_FG><<<dim3(64, NSPL_FG), 256, SMEM_FG>>>();
    sim_mma_kernel<CLDIM, true, NSPL_CLS><<<dim3(64, NSPL_CLS), 256, SMEM_CLS>>>();

    finalize_kernel<<<1, 256>>>((float*)d_out);
}